// round 3
// baseline (speedup 1.0000x reference)
#include <cuda_runtime.h>
#include <math.h>

#define N_TOK 4096
#define CIN   512
#define COUT  512
#define HIDD  128
#define NH    4
#define MIDC  2048
#define LWIN  48

// ---------------- scratch (device globals; no allocation allowed) ----------------
__device__ float g_xn  [N_TOK * CIN];            // LN1(x)
__device__ float g_qkv [3 * NH * N_TOK * HIDD];  // q,k,v  [which][h][n][d]
__device__ float g_o   [NH * N_TOK * HIDD];      // attention output per head
__device__ float g_x1  [N_TOK * COUT];           // o@Wo + x
__device__ float g_h1  [N_TOK * COUT];           // LN2(x1)
__device__ float g_mid [N_TOK * MIDC];           // h1 @ W1
__device__ float g_midn[N_TOK * MIDC];           // relu(LN(mid))

// ---------------- 128x128x8 register-tiled SGEMM body ----------------
// A: [M,K] row-major lda; B: [K,N] row-major ldb; C: [M,N] ldc (+ optional residual, same ldc)
// blockDim = 256. Requires bm+128<=M, bn+128<=N, K%8==0 (all shapes here satisfy this).
__device__ __forceinline__ void gemm_body(
    const float* __restrict__ A, int lda,
    const float* __restrict__ B, int ldb,
    float* __restrict__ C, int ldc,
    const float* __restrict__ Rsd,
    int K, int bm, int bn)
{
    __shared__ float As[8][128];
    __shared__ float Bs[8][128];

    const int tid  = threadIdx.x;
    const int tx   = tid & 15;          // 16 thread-cols
    const int ty   = tid >> 4;          // 16 thread-rows
    const int arow = tid >> 1;          // 0..127
    const int acol = (tid & 1) * 4;     // 0 or 4
    const int brow = tid >> 5;          // 0..7
    const int bcol = (tid & 31) * 4;    // 0..124

    float acc[8][8];
#pragma unroll
    for (int i = 0; i < 8; i++)
#pragma unroll
        for (int j = 0; j < 8; j++) acc[i][j] = 0.f;

    const float* Ap = A + (size_t)(bm + arow) * lda + acol;
    const float* Bp = B + (size_t)brow * ldb + bn + bcol;

    for (int k0 = 0; k0 < K; k0 += 8) {
        float4 a4 = *(const float4*)(Ap + k0);
        float4 b4 = *(const float4*)(Bp + (size_t)k0 * ldb);
        As[acol + 0][arow] = a4.x;
        As[acol + 1][arow] = a4.y;
        As[acol + 2][arow] = a4.z;
        As[acol + 3][arow] = a4.w;
        *(float4*)&Bs[brow][bcol] = b4;
        __syncthreads();

#pragma unroll
        for (int k = 0; k < 8; k++) {
            float4 a0 = *(const float4*)&As[k][ty * 8];
            float4 a1 = *(const float4*)&As[k][ty * 8 + 4];
            float4 b0 = *(const float4*)&Bs[k][tx * 8];
            float4 b1 = *(const float4*)&Bs[k][tx * 8 + 4];
            float av[8] = {a0.x, a0.y, a0.z, a0.w, a1.x, a1.y, a1.z, a1.w};
            float bv[8] = {b0.x, b0.y, b0.z, b0.w, b1.x, b1.y, b1.z, b1.w};
#pragma unroll
            for (int i = 0; i < 8; i++)
#pragma unroll
                for (int j = 0; j < 8; j++)
                    acc[i][j] = fmaf(av[i], bv[j], acc[i][j]);
        }
        __syncthreads();
    }

#pragma unroll
    for (int i = 0; i < 8; i++) {
        const int r = bm + ty * 8 + i;
        float* Cp = C + (size_t)r * ldc + bn + tx * 8;
        float4 o0 = make_float4(acc[i][0], acc[i][1], acc[i][2], acc[i][3]);
        float4 o1 = make_float4(acc[i][4], acc[i][5], acc[i][6], acc[i][7]);
        if (Rsd) {
            const float* Rp = Rsd + (size_t)r * ldc + bn + tx * 8;
            float4 r0 = *(const float4*)Rp;
            float4 r1 = *(const float4*)(Rp + 4);
            o0.x += r0.x; o0.y += r0.y; o0.z += r0.z; o0.w += r0.w;
            o1.x += r1.x; o1.y += r1.y; o1.z += r1.z; o1.w += r1.w;
        }
        *(float4*)Cp = o0;
        *(float4*)(Cp + 4) = o1;
    }
}

__global__ __launch_bounds__(256) void sgemm_kernel(
    const float* __restrict__ A, int lda, const float* __restrict__ B, int ldb,
    float* __restrict__ C, int ldc, const float* __restrict__ Rsd, int K)
{
    gemm_body(A, lda, B, ldb, C, ldc, Rsd, K, blockIdx.y * 128, blockIdx.x * 128);
}

// QKV: z = which*4 + h ; C[h,n,d] = xn @ W_which[h]   (batched: grid.z = 12)
__global__ __launch_bounds__(256) void qkv_kernel(
    const float* __restrict__ Wq, const float* __restrict__ Wk, const float* __restrict__ Wv)
{
    const int z = blockIdx.z;
    const int which = z >> 2, h = z & 3;
    const float* B = (which == 0 ? Wq : which == 1 ? Wk : Wv) + (size_t)h * CIN * HIDD;
    float* C = g_qkv + ((size_t)which * NH + h) * (size_t)N_TOK * HIDD;
    gemm_body(g_xn, CIN, B, HIDD, C, HIDD, nullptr, CIN, blockIdx.y * 128, 0);
}

// Wo + residual x: x1[n, h*128+e] = o_h @ Wo_h + x[n, h*128+e]   (grid.z = 4)
__global__ __launch_bounds__(256) void wo_kernel(
    const float* __restrict__ Wo, const float* __restrict__ xres)
{
    const int h = blockIdx.z;
    gemm_body(g_o + (size_t)h * N_TOK * HIDD, HIDD,
              Wo + (size_t)h * HIDD * HIDD, HIDD,
              g_x1 + h * HIDD, COUT,
              xres + h * HIDD, HIDD, blockIdx.y * 128, 0);
}

// ---------------- LayerNorm (block per row; row kept in registers) ----------------
template <int C, bool RELU>
__global__ __launch_bounds__(128) void ln_kernel(
    const float* __restrict__ x, const float* __restrict__ g,
    const float* __restrict__ b, float* __restrict__ out)
{
    __shared__ float sbuf[4];
    const int tid = threadIdx.x;
    const float* xr = x + (size_t)blockIdx.x * C;
    constexpr int NV = C / 512;   // float4 chunks per thread

    float4 v[NV];
    float s = 0.f;
#pragma unroll
    for (int i = 0; i < NV; i++) {
        v[i] = *(const float4*)(xr + (i * 128 + tid) * 4);
        s += v[i].x + v[i].y + v[i].z + v[i].w;
    }
#pragma unroll
    for (int o2 = 16; o2; o2 >>= 1) s += __shfl_xor_sync(0xffffffffu, s, o2);
    if ((tid & 31) == 0) sbuf[tid >> 5] = s;
    __syncthreads();
    const float mean = (sbuf[0] + sbuf[1] + sbuf[2] + sbuf[3]) * (1.f / C);
    __syncthreads();

    float vs = 0.f;
#pragma unroll
    for (int i = 0; i < NV; i++) {
        float dx;
        dx = v[i].x - mean; vs += dx * dx;
        dx = v[i].y - mean; vs += dx * dx;
        dx = v[i].z - mean; vs += dx * dx;
        dx = v[i].w - mean; vs += dx * dx;
    }
#pragma unroll
    for (int o2 = 16; o2; o2 >>= 1) vs += __shfl_xor_sync(0xffffffffu, vs, o2);
    if ((tid & 31) == 0) sbuf[tid >> 5] = vs;
    __syncthreads();
    const float var  = (sbuf[0] + sbuf[1] + sbuf[2] + sbuf[3]) * (1.f / C);
    const float rstd = 1.f / sqrtf(var + 1e-5f);

    float* orow = out + (size_t)blockIdx.x * C;
#pragma unroll
    for (int i = 0; i < NV; i++) {
        const int idx = (i * 128 + tid) * 4;
        float4 gg = *(const float4*)(g + idx);
        float4 bb = *(const float4*)(b + idx);
        float4 r;
        r.x = (v[i].x - mean) * rstd * gg.x + bb.x;
        r.y = (v[i].y - mean) * rstd * gg.y + bb.y;
        r.z = (v[i].z - mean) * rstd * gg.z + bb.z;
        r.w = (v[i].w - mean) * rstd * gg.w + bb.w;
        if (RELU) {
            r.x = fmaxf(r.x, 0.f); r.y = fmaxf(r.y, 0.f);
            r.z = fmaxf(r.z, 0.f); r.w = fmaxf(r.w, 0.f);
        }
        *(float4*)(orow + idx) = r;
    }
}

// ---------------- banded attention: 1 block / query, 1 warp / head ----------------
// window m in [n-48, n+48]; valid iff batch match && d2<=1. Skipping invalid entries
// is exact: expf(-1e9 - max) == 0 in fp32, so the reference denominator is identical.
__global__ __launch_bounds__(128) void attn_kernel(
    const float* __restrict__ pos, const float* __restrict__ ori,
    const int* __restrict__ batch)
{
    const int n    = blockIdx.x;
    const int h    = threadIdx.x >> 5;
    const int lane = threadIdx.x & 31;
    __shared__ float sc[NH][2 * LWIN + 1];

    const float* q     = g_qkv + ((size_t)h * N_TOK + n) * HIDD;
    const float* kbase = g_qkv + ((size_t)(NH + h)) * (size_t)N_TOK * HIDD;
    const float* vbase = g_qkv + ((size_t)(2 * NH + h)) * (size_t)N_TOK * HIDD;

    const float4 q4 = *(const float4*)(q + lane * 4);
    const float px = pos[3 * n], py = pos[3 * n + 1], pz = pos[3 * n + 2];
    const float ox = ori[3 * n], oy = ori[3 * n + 1], oz = ori[3 * n + 2];
    const int   bn = batch[n];
    const int   m0 = (n - LWIN < 0) ? 0 : n - LWIN;
    const int   m1 = (n + LWIN > N_TOK - 1) ? N_TOK - 1 : n + LWIN;

    float mx = -1e30f;
    for (int m = m0; m <= m1; m++) {
        float s = -1e30f;
        const float dx = pos[3 * m] - px, dy = pos[3 * m + 1] - py, dz = pos[3 * m + 2] - pz;
        if (batch[m] == bn && dx * dx + dy * dy + dz * dz <= 1.0f) {   // uniform branch
            float4 k4 = *(const float4*)(kbase + (size_t)m * HIDD + lane * 4);
            float d = q4.x * k4.x + q4.y * k4.y + q4.z * k4.z + q4.w * k4.w;
#pragma unroll
            for (int o2 = 16; o2; o2 >>= 1) d += __shfl_xor_sync(0xffffffffu, d, o2);
            s = d * 0.08838834764831843f
              + (ox * ori[3 * m] + oy * ori[3 * m + 1] + oz * ori[3 * m + 2]);
            mx = fmaxf(mx, s);
        }
        sc[h][m - m0] = s;
    }
    __syncwarp();

    float  sum = 0.f;
    float4 acc = make_float4(0.f, 0.f, 0.f, 0.f);
    for (int m = m0; m <= m1; m++) {
        const float s = sc[h][m - m0];
        if (s < -1e29f) continue;
        const float p = expf(s - mx);
        sum += p;
        float4 v4 = *(const float4*)(vbase + (size_t)m * HIDD + lane * 4);
        acc.x = fmaf(p, v4.x, acc.x);
        acc.y = fmaf(p, v4.y, acc.y);
        acc.z = fmaf(p, v4.z, acc.z);
        acc.w = fmaf(p, v4.w, acc.w);
    }
    const float inv = 1.f / sum;
    float* op = g_o + ((size_t)h * N_TOK + n) * HIDD;
    *(float4*)(op + lane * 4) =
        make_float4(acc.x * inv, acc.y * inv, acc.z * inv, acc.w * inv);
}

// ---------------- launch ----------------
extern "C" void kernel_launch(void* const* d_in, const int* in_sizes, int n_in,
                              void* d_out, int out_size)
{
    const float* x     = (const float*)d_in[0];
    const float* pos   = (const float*)d_in[1];
    const float* ori   = (const float*)d_in[2];
    // d_in[3] = seq == arange(N): the |ds|<=48 term is handled by the index band.
    const int*   batch = (const int*)d_in[4];
    const float* ln1_g = (const float*)d_in[5];
    const float* ln1_b = (const float*)d_in[6];
    const float* ln2_g = (const float*)d_in[7];
    const float* ln2_b = (const float*)d_in[8];
    const float* Wq    = (const float*)d_in[9];
    const float* Wk    = (const float*)d_in[10];
    const float* Wv    = (const float*)d_in[11];
    const float* Wo    = (const float*)d_in[12];
    const float* lnm_g = (const float*)d_in[13];
    const float* lnm_b = (const float*)d_in[14];
    const float* W1    = (const float*)d_in[15];
    const float* W2    = (const float*)d_in[16];
    float* out = (float*)d_out;

    float *p_xn, *p_x1, *p_h1, *p_mid, *p_midn;
    cudaGetSymbolAddress((void**)&p_xn,   g_xn);
    cudaGetSymbolAddress((void**)&p_x1,   g_x1);
    cudaGetSymbolAddress((void**)&p_h1,   g_h1);
    cudaGetSymbolAddress((void**)&p_mid,  g_mid);
    cudaGetSymbolAddress((void**)&p_midn, g_midn);

    // 1. xn = LN1(x)
    ln_kernel<512, false><<<N_TOK, 128>>>(x, ln1_g, ln1_b, p_xn);

    // 2. Q/K/V projections (batched, 384 CTAs)
    qkv_kernel<<<dim3(1, N_TOK / 128, 12), 256>>>(Wq, Wk, Wv);

    // 3. banded attention
    attn_kernel<<<N_TOK, 128>>>(pos, ori, batch);

    // 4. x1 = concat_h(o_h @ Wo_h) + x
    wo_kernel<<<dim3(1, N_TOK / 128, 4), 256>>>(Wo, x);

    // 5. h1 = LN2(x1)
    ln_kernel<512, false><<<N_TOK, 128>>>(p_x1, ln2_g, ln2_b, p_h1);

    // 6. mid = h1 @ W1
    sgemm_kernel<<<dim3(MIDC / 128, N_TOK / 128), 256>>>(p_h1, CIN, W1, MIDC,
                                                         p_mid, MIDC, nullptr, CIN);

    // 7. midn = relu(LN_mid(mid))
    ln_kernel<2048, true><<<N_TOK, 128>>>(p_mid, lnm_g, lnm_b, p_midn);

    // 8. out = midn @ W2 + x1
    sgemm_kernel<<<dim3(COUT / 128, N_TOK / 128), 256>>>(p_midn, MIDC, W2, COUT,
                                                         out, COUT, p_x1, MIDC);
}

// round 6
// speedup vs baseline: 2.5739x; 2.5739x over previous
#include <cuda_runtime.h>
#include <math.h>

#define N_TOK 4096
#define CIN   512
#define COUT  512
#define HIDD  128
#define NH    4
#define MIDC  2048
#define LWIN  48

// ---------------- scratch (device globals; no allocation allowed) ----------------
__device__ float g_xn  [N_TOK * CIN];            // LN1(x)
__device__ float g_qkv [3 * NH * N_TOK * HIDD];  // q,k,v  [which][h][n][d]
__device__ float g_o   [NH * N_TOK * HIDD];      // attention output per head
__device__ float g_x1  [N_TOK * COUT];           // o@Wo + x
__device__ float g_h1  [N_TOK * COUT];           // LN2(x1)
__device__ float g_mid [N_TOK * MIDC];           // h1 @ W1
__device__ float g_midn[N_TOK * MIDC];           // relu(LN(mid))

// ---------------- TF32 helpers ----------------
__device__ __forceinline__ float f2tf(float x) {
    unsigned r;
    asm("cvt.rna.tf32.f32 %0, %1;" : "=r"(r) : "f"(x));
    return __uint_as_float(r);
}

// ---------------- TF32 tensor-core GEMM: 128x128 tile, BK=16, double-buffered ----
// A: [M,K] row-major lda; B: [K,N] row-major ldb; C += A@B (+ optional residual).
// blockDim = 256 (8 warps, 2x4). Warp tile 64x32 via m16n8k8 HMMA.
#define BK 16
#define AKP 20    // A smem row stride ([m][k] layout): banks (g*20+t)%32 all distinct
#define BNP 136   // B smem row stride ([k][n] layout): 136%32=8 -> banks (8t+g) distinct

__device__ __forceinline__ void gemm_tf32_body(
    const float* __restrict__ A, int lda,
    const float* __restrict__ B, int ldb,
    float* __restrict__ C, int ldc,
    const float* __restrict__ Rsd,
    int K, int bm, int bn)
{
    __shared__ float As[2][128][AKP];
    __shared__ float Bs[2][BK][BNP];

    const int tid   = threadIdx.x;
    const int wid   = tid >> 5;
    const int lane  = tid & 31;
    const int g     = lane >> 2;     // groupID 0..7
    const int tg    = lane & 3;      // thread-in-group 0..3
    const int warpM = wid >> 2;      // 0..1  (64 rows each)
    const int warpN = wid & 3;       // 0..3  (32 cols each)

    const int arow = tid >> 2;       // 0..63  (A gmem load row, +64*i)
    const int acol = (tid & 3) * 4;  // 0,4,8,12
    const int brow = tid >> 5;       // 0..7   (B gmem load row, +8*i)
    const int bcol = (tid & 31) * 4; // 0..124

    float acc[4][4][4];
#pragma unroll
    for (int mi = 0; mi < 4; mi++)
#pragma unroll
        for (int ni = 0; ni < 4; ni++)
#pragma unroll
            for (int r = 0; r < 4; r++) acc[mi][ni][r] = 0.f;

    // ---- preload chunk 0 ----
    {
#pragma unroll
        for (int i = 0; i < 2; i++) {
            float4 a4 = *(const float4*)(A + (size_t)(bm + arow + 64 * i) * lda + acol);
            float4 b4 = *(const float4*)(B + (size_t)(brow + 8 * i) * ldb + bn + bcol);
            float4 ca = make_float4(f2tf(a4.x), f2tf(a4.y), f2tf(a4.z), f2tf(a4.w));
            float4 cb = make_float4(f2tf(b4.x), f2tf(b4.y), f2tf(b4.z), f2tf(b4.w));
            *(float4*)&As[0][arow + 64 * i][acol] = ca;
            *(float4*)&Bs[0][brow + 8 * i][bcol]  = cb;
        }
    }
    __syncthreads();

    int buf = 0;
    for (int k0 = 0; k0 < K; k0 += BK) {
        const bool has_next = (k0 + BK) < K;
        float4 pa[2], pb[2];
        if (has_next) {
            const int kn = k0 + BK;
#pragma unroll
            for (int i = 0; i < 2; i++) {
                pa[i] = *(const float4*)(A + (size_t)(bm + arow + 64 * i) * lda + kn + acol);
                pb[i] = *(const float4*)(B + (size_t)(kn + brow + 8 * i) * ldb + bn + bcol);
            }
        }

        // ---- compute 2 k-steps of 8 ----
#pragma unroll
        for (int ks = 0; ks < 2; ks++) {
            const int kk = ks * 8;
            unsigned af[4][4], bf[4][2];
#pragma unroll
            for (int mi = 0; mi < 4; mi++) {
                const float* ap = &As[buf][warpM * 64 + mi * 16 + g][kk + tg];
                af[mi][0] = __float_as_uint(ap[0]);
                af[mi][1] = __float_as_uint(ap[8 * AKP]);
                af[mi][2] = __float_as_uint(ap[4]);
                af[mi][3] = __float_as_uint(ap[8 * AKP + 4]);
            }
#pragma unroll
            for (int ni = 0; ni < 4; ni++) {
                const float* bp = &Bs[buf][kk + tg][warpN * 32 + ni * 8 + g];
                bf[ni][0] = __float_as_uint(bp[0]);
                bf[ni][1] = __float_as_uint(bp[4 * BNP]);
            }
#pragma unroll
            for (int mi = 0; mi < 4; mi++)
#pragma unroll
                for (int ni = 0; ni < 4; ni++)
                    asm volatile(
                        "mma.sync.aligned.m16n8k8.row.col.f32.tf32.tf32.f32 "
                        "{%0,%1,%2,%3}, {%4,%5,%6,%7}, {%8,%9}, {%0,%1,%2,%3};"
                        : "+f"(acc[mi][ni][0]), "+f"(acc[mi][ni][1]),
                          "+f"(acc[mi][ni][2]), "+f"(acc[mi][ni][3])
                        : "r"(af[mi][0]), "r"(af[mi][1]), "r"(af[mi][2]), "r"(af[mi][3]),
                          "r"(bf[ni][0]), "r"(bf[ni][1]));
        }

        if (has_next) {
#pragma unroll
            for (int i = 0; i < 2; i++) {
                float4 ca = make_float4(f2tf(pa[i].x), f2tf(pa[i].y), f2tf(pa[i].z), f2tf(pa[i].w));
                float4 cb = make_float4(f2tf(pb[i].x), f2tf(pb[i].y), f2tf(pb[i].z), f2tf(pb[i].w));
                *(float4*)&As[buf ^ 1][arow + 64 * i][acol] = ca;
                *(float4*)&Bs[buf ^ 1][brow + 8 * i][bcol]  = cb;
            }
            buf ^= 1;
            __syncthreads();
        }
    }

    // ---- epilogue: C = acc (+ Rsd) ----
#pragma unroll
    for (int mi = 0; mi < 4; mi++) {
        const int r0 = bm + warpM * 64 + mi * 16 + g;
#pragma unroll
        for (int ni = 0; ni < 4; ni++) {
            const int c0 = bn + warpN * 32 + ni * 8 + tg * 2;
            float2 lo = make_float2(acc[mi][ni][0], acc[mi][ni][1]);
            float2 hi = make_float2(acc[mi][ni][2], acc[mi][ni][3]);
            if (Rsd) {
                float2 rl = *(const float2*)(Rsd + (size_t)r0 * ldc + c0);
                float2 rh = *(const float2*)(Rsd + (size_t)(r0 + 8) * ldc + c0);
                lo.x += rl.x; lo.y += rl.y;
                hi.x += rh.x; hi.y += rh.y;
            }
            *(float2*)(C + (size_t)r0 * ldc + c0)       = lo;
            *(float2*)(C + (size_t)(r0 + 8) * ldc + c0) = hi;
        }
    }
}

__global__ __launch_bounds__(256, 2) void sgemm_tf32_kernel(
    const float* __restrict__ A, int lda, const float* __restrict__ B, int ldb,
    float* __restrict__ C, int ldc, const float* __restrict__ Rsd, int K)
{
    gemm_tf32_body(A, lda, B, ldb, C, ldc, Rsd, K, blockIdx.y * 128, blockIdx.x * 128);
}

// QKV: z = which*4 + h ; C[h,n,d] = xn @ W_which[h]   (batched: grid.z = 12)
__global__ __launch_bounds__(256, 2) void qkv_kernel(
    const float* __restrict__ Wq, const float* __restrict__ Wk, const float* __restrict__ Wv)
{
    const int z = blockIdx.z;
    const int which = z >> 2, h = z & 3;
    const float* B = (which == 0 ? Wq : which == 1 ? Wk : Wv) + (size_t)h * CIN * HIDD;
    float* C = g_qkv + ((size_t)which * NH + h) * (size_t)N_TOK * HIDD;
    gemm_tf32_body(g_xn, CIN, B, HIDD, C, HIDD, nullptr, CIN, blockIdx.y * 128, 0);
}

// Wo + residual x: x1[n, h*128+e] = o_h @ Wo_h + x[n, h*128+e]   (grid.z = 4)
__global__ __launch_bounds__(256, 2) void wo_kernel(
    const float* __restrict__ Wo, const float* __restrict__ xres)
{
    const int h = blockIdx.z;
    gemm_tf32_body(g_o + (size_t)h * N_TOK * HIDD, HIDD,
                   Wo + (size_t)h * HIDD * HIDD, HIDD,
                   g_x1 + h * HIDD, COUT,
                   xres + h * HIDD, HIDD, blockIdx.y * 128, 0);
}

// ---------------- LayerNorm (block per row; row kept in registers) ----------------
template <int C, bool RELU>
__global__ __launch_bounds__(128) void ln_kernel(
    const float* __restrict__ x, const float* __restrict__ g,
    const float* __restrict__ b, float* __restrict__ out)
{
    __shared__ float sbuf[4];
    const int tid = threadIdx.x;
    const float* xr = x + (size_t)blockIdx.x * C;
    constexpr int NV = C / 512;   // float4 chunks per thread

    float4 v[NV];
    float s = 0.f;
#pragma unroll
    for (int i = 0; i < NV; i++) {
        v[i] = *(const float4*)(xr + (i * 128 + tid) * 4);
        s += v[i].x + v[i].y + v[i].z + v[i].w;
    }
#pragma unroll
    for (int o2 = 16; o2; o2 >>= 1) s += __shfl_xor_sync(0xffffffffu, s, o2);
    if ((tid & 31) == 0) sbuf[tid >> 5] = s;
    __syncthreads();
    const float mean = (sbuf[0] + sbuf[1] + sbuf[2] + sbuf[3]) * (1.f / C);
    __syncthreads();

    float vs = 0.f;
#pragma unroll
    for (int i = 0; i < NV; i++) {
        float dx;
        dx = v[i].x - mean; vs += dx * dx;
        dx = v[i].y - mean; vs += dx * dx;
        dx = v[i].z - mean; vs += dx * dx;
        dx = v[i].w - mean; vs += dx * dx;
    }
#pragma unroll
    for (int o2 = 16; o2; o2 >>= 1) vs += __shfl_xor_sync(0xffffffffu, vs, o2);
    if ((tid & 31) == 0) sbuf[tid >> 5] = vs;
    __syncthreads();
    const float var  = (sbuf[0] + sbuf[1] + sbuf[2] + sbuf[3]) * (1.f / C);
    const float rstd = 1.f / sqrtf(var + 1e-5f);

    float* orow = out + (size_t)blockIdx.x * C;
#pragma unroll
    for (int i = 0; i < NV; i++) {
        const int idx = (i * 128 + tid) * 4;
        float4 gg = *(const float4*)(g + idx);
        float4 bb = *(const float4*)(b + idx);
        float4 r;
        r.x = (v[i].x - mean) * rstd * gg.x + bb.x;
        r.y = (v[i].y - mean) * rstd * gg.y + bb.y;
        r.z = (v[i].z - mean) * rstd * gg.z + bb.z;
        r.w = (v[i].w - mean) * rstd * gg.w + bb.w;
        if (RELU) {
            r.x = fmaxf(r.x, 0.f); r.y = fmaxf(r.y, 0.f);
            r.z = fmaxf(r.z, 0.f); r.w = fmaxf(r.w, 0.f);
        }
        *(float4*)(orow + idx) = r;
    }
}

// ---------------- banded attention: 1 block / query, 1 warp / head ----------------
// window m in [n-48, n+48]; valid iff batch match && d2<=1. Skipping invalid entries
// is exact: expf(-1e9 - max) == 0 in fp32, so the reference denominator is identical.
__global__ __launch_bounds__(128) void attn_kernel(
    const float* __restrict__ pos, const float* __restrict__ ori,
    const int* __restrict__ batch)
{
    const int n    = blockIdx.x;
    const int h    = threadIdx.x >> 5;
    const int lane = threadIdx.x & 31;
    __shared__ float sc[NH][2 * LWIN + 1];

    const float* q     = g_qkv + ((size_t)h * N_TOK + n) * HIDD;
    const float* kbase = g_qkv + ((size_t)(NH + h)) * (size_t)N_TOK * HIDD;
    const float* vbase = g_qkv + ((size_t)(2 * NH + h)) * (size_t)N_TOK * HIDD;

    const float4 q4 = *(const float4*)(q + lane * 4);
    const float px = pos[3 * n], py = pos[3 * n + 1], pz = pos[3 * n + 2];
    const float ox = ori[3 * n], oy = ori[3 * n + 1], oz = ori[3 * n + 2];
    const int   bn = batch[n];
    const int   m0 = (n - LWIN < 0) ? 0 : n - LWIN;
    const int   m1 = (n + LWIN > N_TOK - 1) ? N_TOK - 1 : n + LWIN;

    float mx = -1e30f;
    for (int m = m0; m <= m1; m++) {
        float s = -1e30f;
        const float dx = pos[3 * m] - px, dy = pos[3 * m + 1] - py, dz = pos[3 * m + 2] - pz;
        if (batch[m] == bn && dx * dx + dy * dy + dz * dz <= 1.0f) {   // uniform branch
            float4 k4 = *(const float4*)(kbase + (size_t)m * HIDD + lane * 4);
            float d = q4.x * k4.x + q4.y * k4.y + q4.z * k4.z + q4.w * k4.w;
#pragma unroll
            for (int o2 = 16; o2; o2 >>= 1) d += __shfl_xor_sync(0xffffffffu, d, o2);
            s = d * 0.08838834764831843f
              + (ox * ori[3 * m] + oy * ori[3 * m + 1] + oz * ori[3 * m + 2]);
            mx = fmaxf(mx, s);
        }
        sc[h][m - m0] = s;
    }
    __syncwarp();

    float  sum = 0.f;
    float4 acc = make_float4(0.f, 0.f, 0.f, 0.f);
    for (int m = m0; m <= m1; m++) {
        const float s = sc[h][m - m0];
        if (s < -1e29f) continue;
        const float p = expf(s - mx);
        sum += p;
        float4 v4 = *(const float4*)(vbase + (size_t)m * HIDD + lane * 4);
        acc.x = fmaf(p, v4.x, acc.x);
        acc.y = fmaf(p, v4.y, acc.y);
        acc.z = fmaf(p, v4.z, acc.z);
        acc.w = fmaf(p, v4.w, acc.w);
    }
    const float inv = 1.f / sum;
    float* op = g_o + ((size_t)h * N_TOK + n) * HIDD;
    *(float4*)(op + lane * 4) =
        make_float4(acc.x * inv, acc.y * inv, acc.z * inv, acc.w * inv);
}

// ---------------- launch ----------------
extern "C" void kernel_launch(void* const* d_in, const int* in_sizes, int n_in,
                              void* d_out, int out_size)
{
    const float* x     = (const float*)d_in[0];
    const float* pos   = (const float*)d_in[1];
    const float* ori   = (const float*)d_in[2];
    // d_in[3] = seq == arange(N): the |ds|<=48 term is handled by the index band.
    const int*   batch = (const int*)d_in[4];
    const float* ln1_g = (const float*)d_in[5];
    const float* ln1_b = (const float*)d_in[6];
    const float* ln2_g = (const float*)d_in[7];
    const float* ln2_b = (const float*)d_in[8];
    const float* Wq    = (const float*)d_in[9];
    const float* Wk    = (const float*)d_in[10];
    const float* Wv    = (const float*)d_in[11];
    const float* Wo    = (const float*)d_in[12];
    const float* lnm_g = (const float*)d_in[13];
    const float* lnm_b = (const float*)d_in[14];
    const float* W1    = (const float*)d_in[15];
    const float* W2    = (const float*)d_in[16];
    float* out = (float*)d_out;

    float *p_xn, *p_x1, *p_h1, *p_mid, *p_midn;
    cudaGetSymbolAddress((void**)&p_xn,   g_xn);
    cudaGetSymbolAddress((void**)&p_x1,   g_x1);
    cudaGetSymbolAddress((void**)&p_h1,   g_h1);
    cudaGetSymbolAddress((void**)&p_mid,  g_mid);
    cudaGetSymbolAddress((void**)&p_midn, g_midn);

    // 1. xn = LN1(x)
    ln_kernel<512, false><<<N_TOK, 128>>>(x, ln1_g, ln1_b, p_xn);

    // 2. Q/K/V projections (batched, 384 CTAs, tf32 tensor cores)
    qkv_kernel<<<dim3(1, N_TOK / 128, 12), 256>>>(Wq, Wk, Wv);

    // 3. banded attention
    attn_kernel<<<N_TOK, 128>>>(pos, ori, batch);

    // 4. x1 = concat_h(o_h @ Wo_h) + x
    wo_kernel<<<dim3(1, N_TOK / 128, 4), 256>>>(Wo, x);

    // 5. h1 = LN2(x1)
    ln_kernel<512, false><<<N_TOK, 128>>>(p_x1, ln2_g, ln2_b, p_h1);

    // 6. mid = h1 @ W1
    sgemm_tf32_kernel<<<dim3(MIDC / 128, N_TOK / 128), 256>>>(p_h1, CIN, W1, MIDC,
                                                              p_mid, MIDC, nullptr, CIN);

    // 7. midn = relu(LN_mid(mid))
    ln_kernel<2048, true><<<N_TOK, 128>>>(p_mid, lnm_g, lnm_b, p_midn);

    // 8. out = midn @ W2 + x1
    sgemm_tf32_kernel<<<dim3(COUT / 128, N_TOK / 128), 256>>>(p_midn, MIDC, W2, COUT,
                                                              out, COUT, p_x1, MIDC);
}

// round 7
// speedup vs baseline: 2.6590x; 1.0331x over previous
#include <cuda_runtime.h>
#include <math.h>

#define N_TOK 4096
#define CIN   512
#define COUT  512
#define HIDD  128
#define NH    4
#define MIDC  2048
#define LWIN  48

// ---------------- scratch (device globals; no allocation allowed) ----------------
__device__ float g_xn  [N_TOK * CIN];            // LN1(x), tf32-rounded
__device__ float g_qkv [3 * NH * N_TOK * HIDD];  // q,k,v  [which][h][n][d] (exact fp32)
__device__ float g_o   [NH * N_TOK * HIDD];      // attention output, tf32-rounded
__device__ float g_x1  [N_TOK * COUT];           // o@Wo + x (exact)
__device__ float g_h1  [N_TOK * COUT];           // LN2(x1), tf32-rounded
__device__ float g_mid [N_TOK * MIDC];           // h1 @ W1 (exact)
__device__ float g_midn[N_TOK * MIDC];           // relu(LN(mid)), tf32-rounded

// pre-rounded weights (tf32 values stored as float)
#define OWQ 0
#define OWK (OWQ + NH * CIN * HIDD)     // 262144
#define OWV (OWK + NH * CIN * HIDD)     // 524288
#define OWO (OWV + NH * CIN * HIDD)     // 786432
#define OW1 (OWO + NH * HIDD * HIDD)    // 851968
#define OW2 (OW1 + COUT * MIDC)         // 1900544
#define WTOT (OW2 + MIDC * COUT)        // 2949120
__device__ float g_w[WTOT];

// ---------------- TF32 helpers ----------------
__device__ __forceinline__ float f2tf(float x) {
    unsigned r;
    asm("cvt.rna.tf32.f32 %0, %1;" : "=r"(r) : "f"(x));
    return __uint_as_float(r);
}

__global__ __launch_bounds__(256) void cvt_kernel(
    const float* __restrict__ Wq, const float* __restrict__ Wk,
    const float* __restrict__ Wv, const float* __restrict__ Wo,
    const float* __restrict__ W1, const float* __restrict__ W2)
{
    const int i = (blockIdx.x * 256 + threadIdx.x) * 4;
    if (i >= WTOT) return;
    const float* src; int off;
    if      (i < OWK) { src = Wq; off = i - OWQ; }
    else if (i < OWV) { src = Wk; off = i - OWK; }
    else if (i < OWO) { src = Wv; off = i - OWV; }
    else if (i < OW1) { src = Wo; off = i - OWO; }
    else if (i < OW2) { src = W1; off = i - OW1; }
    else              { src = W2; off = i - OW2; }
    float4 v = *(const float4*)(src + off);
    float4 r = make_float4(f2tf(v.x), f2tf(v.y), f2tf(v.z), f2tf(v.w));
    *(float4*)(g_w + i) = r;
}

// ---------------- cp.async helpers ----------------
__device__ __forceinline__ unsigned s2u(const void* p) {
    return (unsigned)__cvta_generic_to_shared(p);
}
__device__ __forceinline__ void cpa16(unsigned dst, const void* src) {
    asm volatile("cp.async.cg.shared.global [%0], [%1], 16;\n" :: "r"(dst), "l"(src));
}

// ---------------- TF32 tensor-core GEMM: 128x128 tile, BK=16, cp.async 2-stage ----
// A: [M,K] row-major lda (tf32 values); B: [K,N] row-major ldb (tf32 values);
// C = A@B (+ optional residual). blockDim = 256 (8 warps 2x4), warp tile 64x32.
#define BK 16
#define AKP 20    // A smem row stride ([m][k]): banks (20g+tg)%32 all distinct
#define BNP 136   // B smem row stride ([k][n]): banks (8tg+g) all distinct

__device__ __forceinline__ void gemm_tf32_body(
    const float* __restrict__ A, int lda,
    const float* __restrict__ B, int ldb,
    float* __restrict__ C, int ldc,
    const float* __restrict__ Rsd,
    int K, int bm, int bn)
{
    __shared__ float As[2][128][AKP];
    __shared__ float Bs[2][BK][BNP];

    const int tid   = threadIdx.x;
    const int wid   = tid >> 5;
    const int lane  = tid & 31;
    const int g     = lane >> 2;     // groupID 0..7
    const int tg    = lane & 3;      // thread-in-group 0..3
    const int warpM = wid >> 2;      // 0..1  (64 rows each)
    const int warpN = wid & 3;       // 0..3  (32 cols each)

    const int arow = tid >> 2;       // 0..63
    const int acol = (tid & 3) * 4;  // 0,4,8,12
    const int brow = tid >> 5;       // 0..7
    const int bcol = (tid & 31) * 4; // 0..124

    const float* Agp  = A + (size_t)(bm + arow) * lda + acol;
    const float* Agp2 = Agp + (size_t)64 * lda;
    const float* Bgp  = B + (size_t)brow * ldb + bn + bcol;
    const float* Bgp2 = Bgp + (size_t)8 * ldb;

    const unsigned sa1[2] = { s2u(&As[0][arow][acol]),      s2u(&As[1][arow][acol]) };
    const unsigned sa2[2] = { s2u(&As[0][arow + 64][acol]), s2u(&As[1][arow + 64][acol]) };
    const unsigned sb1[2] = { s2u(&Bs[0][brow][bcol]),      s2u(&Bs[1][brow][bcol]) };
    const unsigned sb2[2] = { s2u(&Bs[0][brow + 8][bcol]),  s2u(&Bs[1][brow + 8][bcol]) };

    float acc[4][4][4];
#pragma unroll
    for (int mi = 0; mi < 4; mi++)
#pragma unroll
        for (int ni = 0; ni < 4; ni++)
#pragma unroll
            for (int r = 0; r < 4; r++) acc[mi][ni][r] = 0.f;

    // prologue: chunk 0 -> slot 0
    cpa16(sa1[0], Agp);
    cpa16(sa2[0], Agp2);
    cpa16(sb1[0], Bgp);
    cpa16(sb2[0], Bgp2);
    asm volatile("cp.async.commit_group;\n" ::: "memory");

    const int nchunks = K / BK;
    for (int c = 0; c < nchunks; c++) {
        asm volatile("cp.async.wait_group 0;\n" ::: "memory");
        __syncthreads();

        if (c + 1 < nchunks) {                 // issue chunk c+1; overlaps compute of c
            const int kn = (c + 1) * BK;
            const int s  = (c + 1) & 1;
            cpa16(sa1[s], Agp + kn);
            cpa16(sa2[s], Agp2 + kn);
            cpa16(sb1[s], Bgp + (size_t)kn * ldb);
            cpa16(sb2[s], Bgp2 + (size_t)kn * ldb);
            asm volatile("cp.async.commit_group;\n" ::: "memory");
        }

        const int buf = c & 1;
#pragma unroll
        for (int ks = 0; ks < 2; ks++) {
            const int kk = ks * 8;
            unsigned af[4][4], bf[4][2];
#pragma unroll
            for (int mi = 0; mi < 4; mi++) {
                const float* ap = &As[buf][warpM * 64 + mi * 16 + g][kk + tg];
                af[mi][0] = __float_as_uint(ap[0]);
                af[mi][1] = __float_as_uint(ap[8 * AKP]);
                af[mi][2] = __float_as_uint(ap[4]);
                af[mi][3] = __float_as_uint(ap[8 * AKP + 4]);
            }
#pragma unroll
            for (int ni = 0; ni < 4; ni++) {
                const float* bp = &Bs[buf][kk + tg][warpN * 32 + ni * 8 + g];
                bf[ni][0] = __float_as_uint(bp[0]);
                bf[ni][1] = __float_as_uint(bp[4 * BNP]);
            }
#pragma unroll
            for (int mi = 0; mi < 4; mi++)
#pragma unroll
                for (int ni = 0; ni < 4; ni++)
                    asm volatile(
                        "mma.sync.aligned.m16n8k8.row.col.f32.tf32.tf32.f32 "
                        "{%0,%1,%2,%3}, {%4,%5,%6,%7}, {%8,%9}, {%0,%1,%2,%3};"
                        : "+f"(acc[mi][ni][0]), "+f"(acc[mi][ni][1]),
                          "+f"(acc[mi][ni][2]), "+f"(acc[mi][ni][3])
                        : "r"(af[mi][0]), "r"(af[mi][1]), "r"(af[mi][2]), "r"(af[mi][3]),
                          "r"(bf[ni][0]), "r"(bf[ni][1]));
        }
    }

    // ---- epilogue: C = acc (+ Rsd) ----
#pragma unroll
    for (int mi = 0; mi < 4; mi++) {
        const int r0 = bm + warpM * 64 + mi * 16 + g;
#pragma unroll
        for (int ni = 0; ni < 4; ni++) {
            const int c0 = bn + warpN * 32 + ni * 8 + tg * 2;
            float2 lo = make_float2(acc[mi][ni][0], acc[mi][ni][1]);
            float2 hi = make_float2(acc[mi][ni][2], acc[mi][ni][3]);
            if (Rsd) {
                float2 rl = *(const float2*)(Rsd + (size_t)r0 * ldc + c0);
                float2 rh = *(const float2*)(Rsd + (size_t)(r0 + 8) * ldc + c0);
                lo.x += rl.x; lo.y += rl.y;
                hi.x += rh.x; hi.y += rh.y;
            }
            *(float2*)(C + (size_t)r0 * ldc + c0)       = lo;
            *(float2*)(C + (size_t)(r0 + 8) * ldc + c0) = hi;
        }
    }
}

__global__ __launch_bounds__(256, 2) void sgemm_tf32_kernel(
    const float* __restrict__ A, int lda, const float* __restrict__ B, int ldb,
    float* __restrict__ C, int ldc, const float* __restrict__ Rsd, int K)
{
    gemm_tf32_body(A, lda, B, ldb, C, ldc, Rsd, K, blockIdx.y * 128, blockIdx.x * 128);
}

// QKV: z = which*4 + h ; C[h,n,d] = xn @ W_which[h]   (batched: grid.z = 12)
__global__ __launch_bounds__(256, 2) void qkv_kernel()
{
    const int z = blockIdx.z;
    const int which = z >> 2, h = z & 3;
    const float* B = g_w + (size_t)which * (NH * CIN * HIDD) + (size_t)h * CIN * HIDD;
    float* C = g_qkv + ((size_t)which * NH + h) * (size_t)N_TOK * HIDD;
    gemm_tf32_body(g_xn, CIN, B, HIDD, C, HIDD, nullptr, CIN, blockIdx.y * 128, 0);
}

// Wo + residual x: x1[n, h*128+e] = o_h @ Wo_h + x[n, h*128+e]   (grid.z = 4)
__global__ __launch_bounds__(256, 2) void wo_kernel(const float* __restrict__ xres)
{
    const int h = blockIdx.z;
    gemm_tf32_body(g_o + (size_t)h * N_TOK * HIDD, HIDD,
                   g_w + OWO + (size_t)h * HIDD * HIDD, HIDD,
                   g_x1 + h * HIDD, COUT,
                   xres + h * HIDD, HIDD, blockIdx.y * 128, 0);
}

// ---------------- LayerNorm (block per row; row kept in registers) ----------------
// TF32OUT: round the stored result to tf32 (consumer is a GEMM A-operand).
template <int C, bool RELU, bool TF32OUT>
__global__ __launch_bounds__(128) void ln_kernel(
    const float* __restrict__ x, const float* __restrict__ g,
    const float* __restrict__ b, float* __restrict__ out)
{
    __shared__ float sbuf[4];
    const int tid = threadIdx.x;
    const float* xr = x + (size_t)blockIdx.x * C;
    constexpr int NV = C / 512;   // float4 chunks per thread

    float4 v[NV];
    float s = 0.f;
#pragma unroll
    for (int i = 0; i < NV; i++) {
        v[i] = *(const float4*)(xr + (i * 128 + tid) * 4);
        s += v[i].x + v[i].y + v[i].z + v[i].w;
    }
#pragma unroll
    for (int o2 = 16; o2; o2 >>= 1) s += __shfl_xor_sync(0xffffffffu, s, o2);
    if ((tid & 31) == 0) sbuf[tid >> 5] = s;
    __syncthreads();
    const float mean = (sbuf[0] + sbuf[1] + sbuf[2] + sbuf[3]) * (1.f / C);
    __syncthreads();

    float vs = 0.f;
#pragma unroll
    for (int i = 0; i < NV; i++) {
        float dx;
        dx = v[i].x - mean; vs += dx * dx;
        dx = v[i].y - mean; vs += dx * dx;
        dx = v[i].z - mean; vs += dx * dx;
        dx = v[i].w - mean; vs += dx * dx;
    }
#pragma unroll
    for (int o2 = 16; o2; o2 >>= 1) vs += __shfl_xor_sync(0xffffffffu, vs, o2);
    if ((tid & 31) == 0) sbuf[tid >> 5] = vs;
    __syncthreads();
    const float var  = (sbuf[0] + sbuf[1] + sbuf[2] + sbuf[3]) * (1.f / C);
    const float rstd = 1.f / sqrtf(var + 1e-5f);

    float* orow = out + (size_t)blockIdx.x * C;
#pragma unroll
    for (int i = 0; i < NV; i++) {
        const int idx = (i * 128 + tid) * 4;
        float4 gg = *(const float4*)(g + idx);
        float4 bb = *(const float4*)(b + idx);
        float4 r;
        r.x = (v[i].x - mean) * rstd * gg.x + bb.x;
        r.y = (v[i].y - mean) * rstd * gg.y + bb.y;
        r.z = (v[i].z - mean) * rstd * gg.z + bb.z;
        r.w = (v[i].w - mean) * rstd * gg.w + bb.w;
        if (RELU) {
            r.x = fmaxf(r.x, 0.f); r.y = fmaxf(r.y, 0.f);
            r.z = fmaxf(r.z, 0.f); r.w = fmaxf(r.w, 0.f);
        }
        if (TF32OUT) {
            r.x = f2tf(r.x); r.y = f2tf(r.y);
            r.z = f2tf(r.z); r.w = f2tf(r.w);
        }
        *(float4*)(orow + idx) = r;
    }
}

// ---------------- banded attention: 1 block / query, 1 warp / head ----------------
// window m in [n-48, n+48]; valid iff batch match && d2<=1. Skipping invalid entries
// is exact: expf(-1e9 - max) == 0 in fp32, so the reference denominator is identical.
__global__ __launch_bounds__(128) void attn_kernel(
    const float* __restrict__ pos, const float* __restrict__ ori,
    const int* __restrict__ batch)
{
    const int n    = blockIdx.x;
    const int h    = threadIdx.x >> 5;
    const int lane = threadIdx.x & 31;
    __shared__ float sc[NH][2 * LWIN + 1];

    const float* q     = g_qkv + ((size_t)h * N_TOK + n) * HIDD;
    const float* kbase = g_qkv + ((size_t)(NH + h)) * (size_t)N_TOK * HIDD;
    const float* vbase = g_qkv + ((size_t)(2 * NH + h)) * (size_t)N_TOK * HIDD;

    const float4 q4 = *(const float4*)(q + lane * 4);
    const float px = pos[3 * n], py = pos[3 * n + 1], pz = pos[3 * n + 2];
    const float ox = ori[3 * n], oy = ori[3 * n + 1], oz = ori[3 * n + 2];
    const int   bn = batch[n];
    const int   m0 = (n - LWIN < 0) ? 0 : n - LWIN;
    const int   m1 = (n + LWIN > N_TOK - 1) ? N_TOK - 1 : n + LWIN;

    float mx = -1e30f;
    for (int m = m0; m <= m1; m++) {
        float s = -1e30f;
        const float dx = pos[3 * m] - px, dy = pos[3 * m + 1] - py, dz = pos[3 * m + 2] - pz;
        if (batch[m] == bn && dx * dx + dy * dy + dz * dz <= 1.0f) {   // uniform branch
            float4 k4 = *(const float4*)(kbase + (size_t)m * HIDD + lane * 4);
            float d = q4.x * k4.x + q4.y * k4.y + q4.z * k4.z + q4.w * k4.w;
#pragma unroll
            for (int o2 = 16; o2; o2 >>= 1) d += __shfl_xor_sync(0xffffffffu, d, o2);
            s = d * 0.08838834764831843f
              + (ox * ori[3 * m] + oy * ori[3 * m + 1] + oz * ori[3 * m + 2]);
            mx = fmaxf(mx, s);
        }
        sc[h][m - m0] = s;
    }
    __syncwarp();

    float  sum = 0.f;
    float4 acc = make_float4(0.f, 0.f, 0.f, 0.f);
    for (int m = m0; m <= m1; m++) {
        const float s = sc[h][m - m0];
        if (s < -1e29f) continue;
        const float p = expf(s - mx);
        sum += p;
        float4 v4 = *(const float4*)(vbase + (size_t)m * HIDD + lane * 4);
        acc.x = fmaf(p, v4.x, acc.x);
        acc.y = fmaf(p, v4.y, acc.y);
        acc.z = fmaf(p, v4.z, acc.z);
        acc.w = fmaf(p, v4.w, acc.w);
    }
    const float inv = 1.f / sum;
    float* op = g_o + ((size_t)h * N_TOK + n) * HIDD;
    *(float4*)(op + lane * 4) =
        make_float4(f2tf(acc.x * inv), f2tf(acc.y * inv),
                    f2tf(acc.z * inv), f2tf(acc.w * inv));
}

// ---------------- launch ----------------
extern "C" void kernel_launch(void* const* d_in, const int* in_sizes, int n_in,
                              void* d_out, int out_size)
{
    const float* x     = (const float*)d_in[0];
    const float* pos   = (const float*)d_in[1];
    const float* ori   = (const float*)d_in[2];
    // d_in[3] = seq == arange(N): the |ds|<=48 term is handled by the index band.
    const int*   batch = (const int*)d_in[4];
    const float* ln1_g = (const float*)d_in[5];
    const float* ln1_b = (const float*)d_in[6];
    const float* ln2_g = (const float*)d_in[7];
    const float* ln2_b = (const float*)d_in[8];
    const float* Wq    = (const float*)d_in[9];
    const float* Wk    = (const float*)d_in[10];
    const float* Wv    = (const float*)d_in[11];
    const float* Wo    = (const float*)d_in[12];
    const float* lnm_g = (const float*)d_in[13];
    const float* lnm_b = (const float*)d_in[14];
    const float* W1    = (const float*)d_in[15];
    const float* W2    = (const float*)d_in[16];
    float* out = (float*)d_out;

    float *p_xn, *p_x1, *p_h1, *p_mid, *p_midn, *p_w;
    cudaGetSymbolAddress((void**)&p_xn,   g_xn);
    cudaGetSymbolAddress((void**)&p_x1,   g_x1);
    cudaGetSymbolAddress((void**)&p_h1,   g_h1);
    cudaGetSymbolAddress((void**)&p_mid,  g_mid);
    cudaGetSymbolAddress((void**)&p_midn, g_midn);
    cudaGetSymbolAddress((void**)&p_w,    g_w);

    // 0. pre-round all weights to tf32 values
    cvt_kernel<<<(WTOT / 4 + 255) / 256, 256>>>(Wq, Wk, Wv, Wo, W1, W2);

    // 1. xn = LN1(x), tf32-rounded
    ln_kernel<512, false, true><<<N_TOK, 128>>>(x, ln1_g, ln1_b, p_xn);

    // 2. Q/K/V projections (batched, 384 CTAs, tf32 tensor cores + cp.async)
    qkv_kernel<<<dim3(1, N_TOK / 128, 12), 256>>>();

    // 3. banded attention (output tf32-rounded for wo)
    attn_kernel<<<N_TOK, 128>>>(pos, ori, batch);

    // 4. x1 = concat_h(o_h @ Wo_h) + x
    wo_kernel<<<dim3(1, N_TOK / 128, 4), 256>>>(x);

    // 5. h1 = LN2(x1), tf32-rounded
    ln_kernel<512, false, true><<<N_TOK, 128>>>(p_x1, ln2_g, ln2_b, p_h1);

    // 6. mid = h1 @ W1
    sgemm_tf32_kernel<<<dim3(MIDC / 128, N_TOK / 128), 256>>>(p_h1, CIN, p_w + OW1, MIDC,
                                                              p_mid, MIDC, nullptr, CIN);

    // 7. midn = relu(LN_mid(mid)), tf32-rounded
    ln_kernel<2048, true, true><<<N_TOK, 128>>>(p_mid, lnm_g, lnm_b, p_midn);

    // 8. out = midn @ W2 + x1
    sgemm_tf32_kernel<<<dim3(COUT / 128, N_TOK / 128), 256>>>(p_midn, MIDC, p_w + OW2, COUT,
                                                              out, COUT, p_x1, MIDC);
}

// round 8
// speedup vs baseline: 3.6583x; 1.3758x over previous
#include <cuda_runtime.h>
#include <math.h>

#define N_TOK 4096
#define CIN   512
#define COUT  512
#define HIDD  128
#define NH    4
#define MIDC  2048
#define LWIN  48

// ---------------- scratch (device globals; no allocation allowed) ----------------
__device__ float g_xn  [N_TOK * CIN];            // LN1(x), tf32-rounded
__device__ float g_qkv [3 * NH * N_TOK * HIDD];  // q,k,v  [which][h][n][d] (exact fp32)
__device__ float g_o   [NH * N_TOK * HIDD];      // attention output, tf32-rounded
__device__ float g_x1  [N_TOK * COUT];           // o@Wo + x (exact)
__device__ float g_h1  [N_TOK * COUT];           // LN2(x1), tf32-rounded
__device__ float g_mid [N_TOK * MIDC];           // h1 @ W1 (exact)
__device__ float g_midn[N_TOK * MIDC];           // relu(LN(mid)), tf32-rounded

// pre-rounded weights (tf32 values stored as float)
#define OWQ 0
#define OWK (OWQ + NH * CIN * HIDD)     // 262144
#define OWV (OWK + NH * CIN * HIDD)     // 524288
#define OWO (OWV + NH * CIN * HIDD)     // 786432
#define OW1 (OWO + NH * HIDD * HIDD)    // 851968
#define OW2 (OW1 + COUT * MIDC)         // 1900544
#define WTOT (OW2 + MIDC * COUT)        // 2949120
__device__ float g_w[WTOT];

// ---------------- TF32 helpers ----------------
__device__ __forceinline__ float f2tf(float x) {
    unsigned r;
    asm("cvt.rna.tf32.f32 %0, %1;" : "=r"(r) : "f"(x));
    return __uint_as_float(r);
}

__global__ __launch_bounds__(256) void cvt_kernel(
    const float* __restrict__ Wq, const float* __restrict__ Wk,
    const float* __restrict__ Wv, const float* __restrict__ Wo,
    const float* __restrict__ W1, const float* __restrict__ W2)
{
    const int i = (blockIdx.x * 256 + threadIdx.x) * 4;
    if (i >= WTOT) return;
    const float* src; int off;
    if      (i < OWK) { src = Wq; off = i - OWQ; }
    else if (i < OWV) { src = Wk; off = i - OWK; }
    else if (i < OWO) { src = Wv; off = i - OWV; }
    else if (i < OW1) { src = Wo; off = i - OWO; }
    else if (i < OW2) { src = W1; off = i - OW1; }
    else              { src = W2; off = i - OW2; }
    float4 v = *(const float4*)(src + off);
    float4 r = make_float4(f2tf(v.x), f2tf(v.y), f2tf(v.z), f2tf(v.w));
    *(float4*)(g_w + i) = r;
}

// ---------------- cp.async helpers ----------------
__device__ __forceinline__ unsigned s2u(const void* p) {
    return (unsigned)__cvta_generic_to_shared(p);
}
__device__ __forceinline__ void cpa16(unsigned dst, const void* src) {
    asm volatile("cp.async.cg.shared.global [%0], [%1], 16;\n" :: "r"(dst), "l"(src));
}

// ---------------- TF32 tensor-core GEMM: 128x128 tile, BK=16, 4-stage cp.async ---
// A: [M,K] row-major lda (tf32 values); B: [K,N] row-major ldb (tf32 values);
// C = A@B (+ optional residual). blockDim = 256 (8 warps 2x4), warp tile 64x32.
#define BK    16
#define AKP   20      // A smem row stride ([m][k]): banks (20g+tg)%32 all distinct
#define BNP   136     // B smem row stride ([k][n]): banks (8tg+g) all distinct
#define NST   4
#define AS_ST (128 * AKP)                 // 2560 floats / stage
#define BS_ST (BK * BNP)                  // 2176 floats / stage
#define GEMM_SMEM (NST * (AS_ST + BS_ST) * 4)   // 75776 bytes

__device__ __forceinline__ void gemm_tf32_body(
    const float* __restrict__ A, int lda,
    const float* __restrict__ B, int ldb,
    float* __restrict__ C, int ldc,
    const float* __restrict__ Rsd,
    int K, int bm, int bn)
{
    extern __shared__ float sm[];
    float* As = sm;                       // [NST][128][AKP]
    float* Bs = sm + NST * AS_ST;         // [NST][BK][BNP]

    const int tid   = threadIdx.x;
    const int wid   = tid >> 5;
    const int lane  = tid & 31;
    const int g     = lane >> 2;     // groupID 0..7
    const int tg    = lane & 3;      // thread-in-group 0..3
    const int warpM = wid >> 2;      // 0..1  (64 rows each)
    const int warpN = wid & 3;       // 0..3  (32 cols each)

    const int arow = tid >> 2;       // 0..63
    const int acol = (tid & 3) * 4;  // 0,4,8,12
    const int brow = tid >> 5;       // 0..7
    const int bcol = (tid & 31) * 4; // 0..124

    const float* Agp  = A + (size_t)(bm + arow) * lda + acol;
    const float* Agp2 = Agp + (size_t)64 * lda;
    const float* Bgp  = B + (size_t)brow * ldb + bn + bcol;
    const float* Bgp2 = Bgp + (size_t)8 * ldb;

    const unsigned saw  = s2u(As + arow * AKP + acol);
    const unsigned saw2 = s2u(As + (arow + 64) * AKP + acol);
    const unsigned sbw  = s2u(Bs + brow * BNP + bcol);
    const unsigned sbw2 = s2u(Bs + (brow + 8) * BNP + bcol);

    const int nchunks = K / BK;

#define ISSUE(c)                                                            \
    do {                                                                    \
        const int _slot = (c) & (NST - 1);                                  \
        const unsigned _ao = _slot * (AS_ST * 4);                           \
        const unsigned _bo = _slot * (BS_ST * 4);                           \
        const int _kn = (c) * BK;                                           \
        cpa16(saw  + _ao, Agp + _kn);                                       \
        cpa16(saw2 + _ao, Agp2 + _kn);                                      \
        cpa16(sbw  + _bo, Bgp + (size_t)_kn * ldb);                         \
        cpa16(sbw2 + _bo, Bgp2 + (size_t)_kn * ldb);                        \
        asm volatile("cp.async.commit_group;\n" ::: "memory");              \
    } while (0)

    float acc[4][4][4];
#pragma unroll
    for (int mi = 0; mi < 4; mi++)
#pragma unroll
        for (int ni = 0; ni < 4; ni++)
#pragma unroll
            for (int r = 0; r < 4; r++) acc[mi][ni][r] = 0.f;

    // prologue: 3 chunks in flight (nchunks >= 8 for all shapes here)
    ISSUE(0);
    ISSUE(1);
    ISSUE(2);

    for (int c = 0; c < nchunks; c++) {
        asm volatile("cp.async.wait_group 2;\n" ::: "memory");
        __syncthreads();

        const float* Asl = As + (c & (NST - 1)) * AS_ST;
        const float* Bsl = Bs + (c & (NST - 1)) * BS_ST;

#pragma unroll
        for (int ks = 0; ks < 2; ks++) {
            const int kk = ks * 8;
            unsigned af[4][4], bf[4][2];
#pragma unroll
            for (int mi = 0; mi < 4; mi++) {
                const float* ap = Asl + (warpM * 64 + mi * 16 + g) * AKP + kk + tg;
                af[mi][0] = __float_as_uint(ap[0]);
                af[mi][1] = __float_as_uint(ap[8 * AKP]);
                af[mi][2] = __float_as_uint(ap[4]);
                af[mi][3] = __float_as_uint(ap[8 * AKP + 4]);
            }
#pragma unroll
            for (int ni = 0; ni < 4; ni++) {
                const float* bp = Bsl + (kk + tg) * BNP + warpN * 32 + ni * 8 + g;
                bf[ni][0] = __float_as_uint(bp[0]);
                bf[ni][1] = __float_as_uint(bp[4 * BNP]);
            }
#pragma unroll
            for (int mi = 0; mi < 4; mi++)
#pragma unroll
                for (int ni = 0; ni < 4; ni++)
                    asm volatile(
                        "mma.sync.aligned.m16n8k8.row.col.f32.tf32.tf32.f32 "
                        "{%0,%1,%2,%3}, {%4,%5,%6,%7}, {%8,%9}, {%0,%1,%2,%3};"
                        : "+f"(acc[mi][ni][0]), "+f"(acc[mi][ni][1]),
                          "+f"(acc[mi][ni][2]), "+f"(acc[mi][ni][3])
                        : "r"(af[mi][0]), "r"(af[mi][1]), "r"(af[mi][2]), "r"(af[mi][3]),
                          "r"(bf[ni][0]), "r"(bf[ni][1]));
        }

        // keep commit-group count in lockstep (empty group at the tail)
        if (c + 3 < nchunks) {
            ISSUE(c + 3);
        } else {
            asm volatile("cp.async.commit_group;\n" ::: "memory");
        }
    }
#undef ISSUE

    // ---- epilogue: C = acc (+ Rsd) ----
#pragma unroll
    for (int mi = 0; mi < 4; mi++) {
        const int r0 = bm + warpM * 64 + mi * 16 + g;
#pragma unroll
        for (int ni = 0; ni < 4; ni++) {
            const int c0 = bn + warpN * 32 + ni * 8 + tg * 2;
            float2 lo = make_float2(acc[mi][ni][0], acc[mi][ni][1]);
            float2 hi = make_float2(acc[mi][ni][2], acc[mi][ni][3]);
            if (Rsd) {
                float2 rl = *(const float2*)(Rsd + (size_t)r0 * ldc + c0);
                float2 rh = *(const float2*)(Rsd + (size_t)(r0 + 8) * ldc + c0);
                lo.x += rl.x; lo.y += rl.y;
                hi.x += rh.x; hi.y += rh.y;
            }
            *(float2*)(C + (size_t)r0 * ldc + c0)       = lo;
            *(float2*)(C + (size_t)(r0 + 8) * ldc + c0) = hi;
        }
    }
}

__global__ __launch_bounds__(256, 2) void sgemm_tf32_kernel(
    const float* __restrict__ A, int lda, const float* __restrict__ B, int ldb,
    float* __restrict__ C, int ldc, const float* __restrict__ Rsd, int K)
{
    gemm_tf32_body(A, lda, B, ldb, C, ldc, Rsd, K, blockIdx.y * 128, blockIdx.x * 128);
}

// QKV: z = which*4 + h ; C[h,n,d] = xn @ W_which[h]   (batched: grid.z = 12)
__global__ __launch_bounds__(256, 2) void qkv_kernel()
{
    const int z = blockIdx.z;
    const int which = z >> 2, h = z & 3;
    const float* B = g_w + (size_t)which * (NH * CIN * HIDD) + (size_t)h * CIN * HIDD;
    float* C = g_qkv + ((size_t)which * NH + h) * (size_t)N_TOK * HIDD;
    gemm_tf32_body(g_xn, CIN, B, HIDD, C, HIDD, nullptr, CIN, blockIdx.y * 128, 0);
}

// Wo + residual x: x1[n, h*128+e] = o_h @ Wo_h + x[n, h*128+e]   (grid.z = 4)
__global__ __launch_bounds__(256, 2) void wo_kernel(const float* __restrict__ xres)
{
    const int h = blockIdx.z;
    gemm_tf32_body(g_o + (size_t)h * N_TOK * HIDD, HIDD,
                   g_w + OWO + (size_t)h * HIDD * HIDD, HIDD,
                   g_x1 + h * HIDD, COUT,
                   xres + h * HIDD, HIDD, blockIdx.y * 128, 0);
}

// ---------------- LayerNorm (block per row; row kept in registers) ----------------
// TF32OUT: round the stored result to tf32 (consumer is a GEMM A-operand).
template <int C, bool RELU, bool TF32OUT>
__global__ __launch_bounds__(128) void ln_kernel(
    const float* __restrict__ x, const float* __restrict__ g,
    const float* __restrict__ b, float* __restrict__ out)
{
    __shared__ float sbuf[4];
    const int tid = threadIdx.x;
    const float* xr = x + (size_t)blockIdx.x * C;
    constexpr int NV = C / 512;   // float4 chunks per thread

    float4 v[NV];
    float s = 0.f;
#pragma unroll
    for (int i = 0; i < NV; i++) {
        v[i] = *(const float4*)(xr + (i * 128 + tid) * 4);
        s += v[i].x + v[i].y + v[i].z + v[i].w;
    }
#pragma unroll
    for (int o2 = 16; o2; o2 >>= 1) s += __shfl_xor_sync(0xffffffffu, s, o2);
    if ((tid & 31) == 0) sbuf[tid >> 5] = s;
    __syncthreads();
    const float mean = (sbuf[0] + sbuf[1] + sbuf[2] + sbuf[3]) * (1.f / C);
    __syncthreads();

    float vs = 0.f;
#pragma unroll
    for (int i = 0; i < NV; i++) {
        float dx;
        dx = v[i].x - mean; vs += dx * dx;
        dx = v[i].y - mean; vs += dx * dx;
        dx = v[i].z - mean; vs += dx * dx;
        dx = v[i].w - mean; vs += dx * dx;
    }
#pragma unroll
    for (int o2 = 16; o2; o2 >>= 1) vs += __shfl_xor_sync(0xffffffffu, vs, o2);
    if ((tid & 31) == 0) sbuf[tid >> 5] = vs;
    __syncthreads();
    const float var  = (sbuf[0] + sbuf[1] + sbuf[2] + sbuf[3]) * (1.f / C);
    const float rstd = 1.f / sqrtf(var + 1e-5f);

    float* orow = out + (size_t)blockIdx.x * C;
#pragma unroll
    for (int i = 0; i < NV; i++) {
        const int idx = (i * 128 + tid) * 4;
        float4 gg = *(const float4*)(g + idx);
        float4 bb = *(const float4*)(b + idx);
        float4 r;
        r.x = (v[i].x - mean) * rstd * gg.x + bb.x;
        r.y = (v[i].y - mean) * rstd * gg.y + bb.y;
        r.z = (v[i].z - mean) * rstd * gg.z + bb.z;
        r.w = (v[i].w - mean) * rstd * gg.w + bb.w;
        if (RELU) {
            r.x = fmaxf(r.x, 0.f); r.y = fmaxf(r.y, 0.f);
            r.z = fmaxf(r.z, 0.f); r.w = fmaxf(r.w, 0.f);
        }
        if (TF32OUT) {
            r.x = f2tf(r.x); r.y = f2tf(r.y);
            r.z = f2tf(r.z); r.w = f2tf(r.w);
        }
        *(float4*)(orow + idx) = r;
    }
}

// ---------------- banded attention: 1 block / query, 1 warp / head ----------------
// Phase A: mask+gbias computed ONCE per (n,m) pair (head-independent), in smem.
// Phase B: per-head single pass with online softmax (rescale on new max).
// Skipping masked entries is exact: expf(-1e9 - max) == 0 in fp32.
__global__ __launch_bounds__(128) void attn_kernel(
    const float* __restrict__ pos, const float* __restrict__ ori,
    const int* __restrict__ batch)
{
    const int n    = blockIdx.x;
    const int tid  = threadIdx.x;
    const int h    = tid >> 5;
    const int lane = tid & 31;
    __shared__ float base[2 * LWIN + 1];

    const int m0  = (n - LWIN < 0) ? 0 : n - LWIN;
    const int m1  = (n + LWIN > N_TOK - 1) ? N_TOK - 1 : n + LWIN;
    const int cnt = m1 - m0 + 1;

    // ---- phase A: head-independent mask + orientation bias ----
    if (tid < cnt) {
        const int m = m0 + tid;
        const float dx = pos[3 * m]     - pos[3 * n];
        const float dy = pos[3 * m + 1] - pos[3 * n + 1];
        const float dz = pos[3 * m + 2] - pos[3 * n + 2];
        const bool ok = (batch[m] == batch[n]) && (dx * dx + dy * dy + dz * dz <= 1.0f);
        base[tid] = ok ? (ori[3 * n]     * ori[3 * m] +
                          ori[3 * n + 1] * ori[3 * m + 1] +
                          ori[3 * n + 2] * ori[3 * m + 2])
                       : -1e30f;
    }
    __syncthreads();

    // ---- phase B: per-head online softmax, single pass ----
    const float* q     = g_qkv + ((size_t)h * N_TOK + n) * HIDD;
    const float* kbase = g_qkv + ((size_t)(NH + h)) * (size_t)N_TOK * HIDD;
    const float* vbase = g_qkv + ((size_t)(2 * NH + h)) * (size_t)N_TOK * HIDD;

    const float4 q4 = *(const float4*)(q + lane * 4);

    float  mx  = -1e30f;
    float  sum = 0.f;
    float4 acc = make_float4(0.f, 0.f, 0.f, 0.f);

    for (int j = 0; j < cnt; j++) {
        const float b = base[j];
        if (b < -1e29f) continue;          // warp-uniform skip
        const int m = m0 + j;

        float4 k4 = *(const float4*)(kbase + (size_t)m * HIDD + lane * 4);
        float d = q4.x * k4.x + q4.y * k4.y + q4.z * k4.z + q4.w * k4.w;
#pragma unroll
        for (int o2 = 16; o2; o2 >>= 1) d += __shfl_xor_sync(0xffffffffu, d, o2);
        const float s = d * 0.08838834764831843f + b;

        float4 v4 = *(const float4*)(vbase + (size_t)m * HIDD + lane * 4);
        if (s > mx) {                      // warp-uniform (s identical on all lanes)
            const float corr = expf(mx - s);   // 0 on first valid neighbor
            sum = sum * corr + 1.f;
            acc.x = acc.x * corr + v4.x;
            acc.y = acc.y * corr + v4.y;
            acc.z = acc.z * corr + v4.z;
            acc.w = acc.w * corr + v4.w;
            mx = s;
        } else {
            const float p = expf(s - mx);
            sum += p;
            acc.x = fmaf(p, v4.x, acc.x);
            acc.y = fmaf(p, v4.y, acc.y);
            acc.z = fmaf(p, v4.z, acc.z);
            acc.w = fmaf(p, v4.w, acc.w);
        }
    }

    const float inv = 1.f / sum;
    float* op = g_o + ((size_t)h * N_TOK + n) * HIDD;
    *(float4*)(op + lane * 4) =
        make_float4(f2tf(acc.x * inv), f2tf(acc.y * inv),
                    f2tf(acc.z * inv), f2tf(acc.w * inv));
}

// ---------------- launch ----------------
extern "C" void kernel_launch(void* const* d_in, const int* in_sizes, int n_in,
                              void* d_out, int out_size)
{
    const float* x     = (const float*)d_in[0];
    const float* pos   = (const float*)d_in[1];
    const float* ori   = (const float*)d_in[2];
    // d_in[3] = seq == arange(N): the |ds|<=48 term is handled by the index band.
    const int*   batch = (const int*)d_in[4];
    const float* ln1_g = (const float*)d_in[5];
    const float* ln1_b = (const float*)d_in[6];
    const float* ln2_g = (const float*)d_in[7];
    const float* ln2_b = (const float*)d_in[8];
    const float* Wq    = (const float*)d_in[9];
    const float* Wk    = (const float*)d_in[10];
    const float* Wv    = (const float*)d_in[11];
    const float* Wo    = (const float*)d_in[12];
    const float* lnm_g = (const float*)d_in[13];
    const float* lnm_b = (const float*)d_in[14];
    const float* W1    = (const float*)d_in[15];
    const float* W2    = (const float*)d_in[16];
    float* out = (float*)d_out;

    float *p_xn, *p_x1, *p_h1, *p_mid, *p_midn, *p_w;
    cudaGetSymbolAddress((void**)&p_xn,   g_xn);
    cudaGetSymbolAddress((void**)&p_x1,   g_x1);
    cudaGetSymbolAddress((void**)&p_h1,   g_h1);
    cudaGetSymbolAddress((void**)&p_mid,  g_mid);
    cudaGetSymbolAddress((void**)&p_midn, g_midn);
    cudaGetSymbolAddress((void**)&p_w,    g_w);

    // allow 75.8KB dynamic smem on the GEMM kernels (idempotent, capture-safe)
    static bool attr_done = false;
    if (!attr_done) {
        cudaFuncSetAttribute(sgemm_tf32_kernel,
                             cudaFuncAttributeMaxDynamicSharedMemorySize, GEMM_SMEM);
        cudaFuncSetAttribute(qkv_kernel,
                             cudaFuncAttributeMaxDynamicSharedMemorySize, GEMM_SMEM);
        cudaFuncSetAttribute(wo_kernel,
                             cudaFuncAttributeMaxDynamicSharedMemorySize, GEMM_SMEM);
        attr_done = true;
    }

    // 0. pre-round all weights to tf32 values
    cvt_kernel<<<(WTOT / 4 + 255) / 256, 256>>>(Wq, Wk, Wv, Wo, W1, W2);

    // 1. xn = LN1(x), tf32-rounded
    ln_kernel<512, false, true><<<N_TOK, 128>>>(x, ln1_g, ln1_b, p_xn);

    // 2. Q/K/V projections (batched, 384 CTAs, tf32 tensor cores + 4-stage cp.async)
    qkv_kernel<<<dim3(1, N_TOK / 128, 12), 256, GEMM_SMEM>>>();

    // 3. banded attention (single pass, shared mask/bias)
    attn_kernel<<<N_TOK, 128>>>(pos, ori, batch);

    // 4. x1 = concat_h(o_h @ Wo_h) + x
    wo_kernel<<<dim3(1, N_TOK / 128, 4), 256, GEMM_SMEM>>>(x);

    // 5. h1 = LN2(x1), tf32-rounded
    ln_kernel<512, false, true><<<N_TOK, 128>>>(p_x1, ln2_g, ln2_b, p_h1);

    // 6. mid = h1 @ W1
    sgemm_tf32_kernel<<<dim3(MIDC / 128, N_TOK / 128), 256, GEMM_SMEM>>>(
        p_h1, CIN, p_w + OW1, MIDC, p_mid, MIDC, nullptr, CIN);

    // 7. midn = relu(LN_mid(mid)), tf32-rounded
    ln_kernel<2048, true, true><<<N_TOK, 128>>>(p_mid, lnm_g, lnm_b, p_midn);

    // 8. out = midn @ W2 + x1
    sgemm_tf32_kernel<<<dim3(COUT / 128, N_TOK / 128), 256, GEMM_SMEM>>>(
        p_midn, MIDC, p_w + OW2, COUT, out, COUT, p_x1, MIDC);
}

// round 9
// speedup vs baseline: 4.5021x; 1.2307x over previous
#include <cuda_runtime.h>
#include <cuda_fp16.h>
#include <math.h>

#define N_TOK 4096
#define CIN   512
#define COUT  512
#define HIDD  128
#define NH    4
#define MIDC  2048
#define LWIN  48

// ---------------- scratch (device globals; no allocation allowed) ----------------
__device__ __half g_xnh [N_TOK * CIN];           // LN1(x), fp16
__device__ float  g_qkv [3 * NH * N_TOK * HIDD]; // q,k,v  [which][h][n][d] fp32
__device__ __half g_oh  [NH * N_TOK * HIDD];     // attention output, fp16
__device__ float  g_x1  [N_TOK * COUT];          // o@Wo + x (exact fp32)
__device__ __half g_h1h [N_TOK * COUT];          // LN2(x1), fp16
__device__ float  g_mid [N_TOK * MIDC];          // h1 @ W1 (fp32)
__device__ __half g_midnh[N_TOK * MIDC];         // relu(LN(mid)), fp16

// pre-transposed fp16 weights: each matrix stored [N][K] row-major
#define OWQ 0
#define OWK (OWQ + NH * CIN * HIDD)     // 262144
#define OWV (OWK + NH * CIN * HIDD)     // 524288
#define OWO (OWV + NH * CIN * HIDD)     // 786432
#define OW1 (OWO + NH * HIDD * HIDD)    // 851968
#define OW2 (OW1 + COUT * MIDC)         // 1900544
#define WTOT (OW2 + MIDC * COUT)        // 2949120
__device__ __half g_wh[WTOT];

// ---------------- weight transpose+convert: dst[n][k] = (half)src[k][n] ----------
__global__ __launch_bounds__(256) void transpose_h_kernel(
    const float* __restrict__ src, __half* __restrict__ dst, int K, int N)
{
    __shared__ float t[32][33];
    const int k0 = blockIdx.x * 32, n0 = blockIdx.y * 32;
    src += (size_t)blockIdx.z * K * N;
    dst += (size_t)blockIdx.z * K * N;
    const int tx = threadIdx.x, ty = threadIdx.y;   // (32, 8)
#pragma unroll
    for (int i = 0; i < 32; i += 8)
        t[ty + i][tx] = src[(size_t)(k0 + ty + i) * N + n0 + tx];
    __syncthreads();
#pragma unroll
    for (int i = 0; i < 32; i += 8)
        dst[(size_t)(n0 + ty + i) * K + k0 + tx] = __float2half_rn(t[tx][ty + i]);
}

// ---------------- cp.async helpers ----------------
__device__ __forceinline__ unsigned s2u(const void* p) {
    return (unsigned)__cvta_generic_to_shared(p);
}
__device__ __forceinline__ void cpa16(unsigned dst, const void* src) {
    asm volatile("cp.async.cg.shared.global [%0], [%1], 16;\n" :: "r"(dst), "l"(src));
}

// ---------------- FP16 tensor-core GEMM: 128x128 tile, BK=32, 4-stage cp.async ---
// A: [M,K] row-major fp16; Bt: [N,K] row-major fp16 (pre-transposed weight);
// C = A@B (+ optional fp32 residual). blockDim=256 (8 warps 2x4), warp tile 64x32,
// mma.m16n8k16. Every fragment register is one contiguous half2 -> 1 LDS.32.
#define BKH  32
#define RS   40                          // smem row stride in halves (80B: banks (20g+tg)%32 distinct)
#define NST  4
#define A_ST (128 * RS)                  // halves per stage (A and B identical)
#define GEMM_SMEM (NST * 2 * A_ST * 2)   // 81920 bytes

__device__ __forceinline__ void gemm_f16_body(
    const __half* __restrict__ A, int lda,
    const __half* __restrict__ Bt, int ldbt,
    float* __restrict__ C, int ldc,
    const float* __restrict__ Rsd,
    int K, int bm, int bn)
{
    extern __shared__ __half smh[];
    __half* As = smh;                    // [NST][128][RS]
    __half* Bs = smh + NST * A_ST;       // [NST][128][RS]

    const int tid   = threadIdx.x;
    const int wid   = tid >> 5;
    const int lane  = tid & 31;
    const int g     = lane >> 2;     // 0..7
    const int tg    = lane & 3;      // 0..3
    const int warpM = wid >> 2;      // 0..1  (64 rows)
    const int warpN = wid & 3;       // 0..3  (32 cols)

    const int lrow = tid >> 1;               // 0..127 (load row, A and B)
    const int lseg = (tid & 1) * 8;          // halves: 0 or 8

    const __half* Agp = A  + (size_t)(bm + lrow) * lda  + lseg;
    const __half* Bgp = Bt + (size_t)(bn + lrow) * ldbt + lseg;
    const unsigned saw = s2u(As + lrow * RS + lseg);
    const unsigned sbw = s2u(Bs + lrow * RS + lseg);

    const int nchunks = K / BKH;

#define ISSUE(c)                                                            \
    do {                                                                    \
        const unsigned _off = ((c) & (NST - 1)) * (A_ST * 2);               \
        const int _kn = (c) * BKH;                                          \
        cpa16(saw + _off,      Agp + _kn);                                  \
        cpa16(saw + _off + 32, Agp + _kn + 16);                             \
        cpa16(sbw + _off,      Bgp + _kn);                                  \
        cpa16(sbw + _off + 32, Bgp + _kn + 16);                             \
        asm volatile("cp.async.commit_group;\n" ::: "memory");              \
    } while (0)

    float acc[4][4][4];
#pragma unroll
    for (int mi = 0; mi < 4; mi++)
#pragma unroll
        for (int ni = 0; ni < 4; ni++)
#pragma unroll
            for (int r = 0; r < 4; r++) acc[mi][ni][r] = 0.f;

    // prologue: 3 chunks in flight (nchunks >= 4 for all shapes here)
    ISSUE(0);
    ISSUE(1);
    ISSUE(2);

    for (int c = 0; c < nchunks; c++) {
        asm volatile("cp.async.wait_group 2;\n" ::: "memory");
        __syncthreads();

        const __half* Asl = As + (c & (NST - 1)) * A_ST;
        const __half* Bsl = Bs + (c & (NST - 1)) * A_ST;

#pragma unroll
        for (int ks = 0; ks < 2; ks++) {
            const int kk = ks * 16;
            unsigned af[4][4], bf[4][2];
#pragma unroll
            for (int mi = 0; mi < 4; mi++) {
                const __half* ap = Asl + (warpM * 64 + mi * 16 + g) * RS + kk + tg * 2;
                af[mi][0] = *(const unsigned*)(ap);
                af[mi][1] = *(const unsigned*)(ap + 8 * RS);
                af[mi][2] = *(const unsigned*)(ap + 8);
                af[mi][3] = *(const unsigned*)(ap + 8 * RS + 8);
            }
#pragma unroll
            for (int ni = 0; ni < 4; ni++) {
                const __half* bp = Bsl + (warpN * 32 + ni * 8 + g) * RS + kk + tg * 2;
                bf[ni][0] = *(const unsigned*)(bp);
                bf[ni][1] = *(const unsigned*)(bp + 8);
            }
#pragma unroll
            for (int mi = 0; mi < 4; mi++)
#pragma unroll
                for (int ni = 0; ni < 4; ni++)
                    asm volatile(
                        "mma.sync.aligned.m16n8k16.row.col.f32.f16.f16.f32 "
                        "{%0,%1,%2,%3}, {%4,%5,%6,%7}, {%8,%9}, {%0,%1,%2,%3};"
                        : "+f"(acc[mi][ni][0]), "+f"(acc[mi][ni][1]),
                          "+f"(acc[mi][ni][2]), "+f"(acc[mi][ni][3])
                        : "r"(af[mi][0]), "r"(af[mi][1]), "r"(af[mi][2]), "r"(af[mi][3]),
                          "r"(bf[ni][0]), "r"(bf[ni][1]));
        }

        // keep commit-group count in lockstep (empty group at the tail)
        if (c + 3 < nchunks) {
            ISSUE(c + 3);
        } else {
            asm volatile("cp.async.commit_group;\n" ::: "memory");
        }
    }
#undef ISSUE

    // ---- epilogue: C = acc (+ Rsd) ----
#pragma unroll
    for (int mi = 0; mi < 4; mi++) {
        const int r0 = bm + warpM * 64 + mi * 16 + g;
#pragma unroll
        for (int ni = 0; ni < 4; ni++) {
            const int c0 = bn + warpN * 32 + ni * 8 + tg * 2;
            float2 lo = make_float2(acc[mi][ni][0], acc[mi][ni][1]);
            float2 hi = make_float2(acc[mi][ni][2], acc[mi][ni][3]);
            if (Rsd) {
                float2 rl = *(const float2*)(Rsd + (size_t)r0 * ldc + c0);
                float2 rh = *(const float2*)(Rsd + (size_t)(r0 + 8) * ldc + c0);
                lo.x += rl.x; lo.y += rl.y;
                hi.x += rh.x; hi.y += rh.y;
            }
            *(float2*)(C + (size_t)r0 * ldc + c0)       = lo;
            *(float2*)(C + (size_t)(r0 + 8) * ldc + c0) = hi;
        }
    }
}

__global__ __launch_bounds__(256, 2) void sgemm_f16_kernel(
    const __half* __restrict__ A, int lda, const __half* __restrict__ Bt, int ldbt,
    float* __restrict__ C, int ldc, const float* __restrict__ Rsd, int K)
{
    gemm_f16_body(A, lda, Bt, ldbt, C, ldc, Rsd, K, blockIdx.y * 128, blockIdx.x * 128);
}

// QKV: z = which*4 + h ; C[h,n,d] = xn @ W_which[h]   (batched: grid.z = 12)
__global__ __launch_bounds__(256, 2) void qkv_kernel()
{
    const int z = blockIdx.z;
    const int which = z >> 2, h = z & 3;
    const __half* Bt = g_wh + (size_t)which * (NH * CIN * HIDD) + (size_t)h * CIN * HIDD;
    float* C = g_qkv + ((size_t)which * NH + h) * (size_t)N_TOK * HIDD;
    gemm_f16_body(g_xnh, CIN, Bt, CIN, C, HIDD, nullptr, CIN, blockIdx.y * 128, 0);
}

// Wo + residual x: x1[n, h*128+e] = o_h @ Wo_h + x[n, h*128+e]   (grid.z = 4)
__global__ __launch_bounds__(256, 2) void wo_kernel(const float* __restrict__ xres)
{
    const int h = blockIdx.z;
    gemm_f16_body(g_oh + (size_t)h * N_TOK * HIDD, HIDD,
                  g_wh + OWO + (size_t)h * HIDD * HIDD, HIDD,
                  g_x1 + h * HIDD, COUT,
                  xres + h * HIDD, HIDD, blockIdx.y * 128, 0);
}

// ---------------- LayerNorm (block per row; row in registers; fp16 output) -------
template <int C, bool RELU>
__global__ __launch_bounds__(128) void ln_kernel(
    const float* __restrict__ x, const float* __restrict__ g,
    const float* __restrict__ b, __half* __restrict__ out)
{
    __shared__ float sbuf[4];
    const int tid = threadIdx.x;
    const float* xr = x + (size_t)blockIdx.x * C;
    constexpr int NV = C / 512;   // float4 chunks per thread

    float4 v[NV];
    float s = 0.f;
#pragma unroll
    for (int i = 0; i < NV; i++) {
        v[i] = *(const float4*)(xr + (i * 128 + tid) * 4);
        s += v[i].x + v[i].y + v[i].z + v[i].w;
    }
#pragma unroll
    for (int o2 = 16; o2; o2 >>= 1) s += __shfl_xor_sync(0xffffffffu, s, o2);
    if ((tid & 31) == 0) sbuf[tid >> 5] = s;
    __syncthreads();
    const float mean = (sbuf[0] + sbuf[1] + sbuf[2] + sbuf[3]) * (1.f / C);
    __syncthreads();

    float vs = 0.f;
#pragma unroll
    for (int i = 0; i < NV; i++) {
        float dx;
        dx = v[i].x - mean; vs += dx * dx;
        dx = v[i].y - mean; vs += dx * dx;
        dx = v[i].z - mean; vs += dx * dx;
        dx = v[i].w - mean; vs += dx * dx;
    }
#pragma unroll
    for (int o2 = 16; o2; o2 >>= 1) vs += __shfl_xor_sync(0xffffffffu, vs, o2);
    if ((tid & 31) == 0) sbuf[tid >> 5] = vs;
    __syncthreads();
    const float var  = (sbuf[0] + sbuf[1] + sbuf[2] + sbuf[3]) * (1.f / C);
    const float rstd = 1.f / sqrtf(var + 1e-5f);

    __half* orow = out + (size_t)blockIdx.x * C;
#pragma unroll
    for (int i = 0; i < NV; i++) {
        const int idx = (i * 128 + tid) * 4;
        float4 gg = *(const float4*)(g + idx);
        float4 bb = *(const float4*)(b + idx);
        float4 r;
        r.x = (v[i].x - mean) * rstd * gg.x + bb.x;
        r.y = (v[i].y - mean) * rstd * gg.y + bb.y;
        r.z = (v[i].z - mean) * rstd * gg.z + bb.z;
        r.w = (v[i].w - mean) * rstd * gg.w + bb.w;
        if (RELU) {
            r.x = fmaxf(r.x, 0.f); r.y = fmaxf(r.y, 0.f);
            r.z = fmaxf(r.z, 0.f); r.w = fmaxf(r.w, 0.f);
        }
        __half2 h0 = __float22half2_rn(make_float2(r.x, r.y));
        __half2 h1 = __float22half2_rn(make_float2(r.z, r.w));
        *(__half2*)(orow + idx)     = h0;
        *(__half2*)(orow + idx + 2) = h1;
    }
}

// ---------------- banded attention: 1 block / query, 1 warp / head ----------------
// Phase A: mask+gbias computed ONCE per (n,m) pair (head-independent), in smem.
// Phase B: per-head single pass with online softmax (rescale on new max).
// Skipping masked entries is exact: expf(-1e9 - max) == 0 in fp32.
__global__ __launch_bounds__(128) void attn_kernel(
    const float* __restrict__ pos, const float* __restrict__ ori,
    const int* __restrict__ batch)
{
    const int n    = blockIdx.x;
    const int tid  = threadIdx.x;
    const int h    = tid >> 5;
    const int lane = tid & 31;
    __shared__ float base[2 * LWIN + 1];

    const int m0  = (n - LWIN < 0) ? 0 : n - LWIN;
    const int m1  = (n + LWIN > N_TOK - 1) ? N_TOK - 1 : n + LWIN;
    const int cnt = m1 - m0 + 1;

    // ---- phase A: head-independent mask + orientation bias ----
    if (tid < cnt) {
        const int m = m0 + tid;
        const float dx = pos[3 * m]     - pos[3 * n];
        const float dy = pos[3 * m + 1] - pos[3 * n + 1];
        const float dz = pos[3 * m + 2] - pos[3 * n + 2];
        const bool ok = (batch[m] == batch[n]) && (dx * dx + dy * dy + dz * dz <= 1.0f);
        base[tid] = ok ? (ori[3 * n]     * ori[3 * m] +
                          ori[3 * n + 1] * ori[3 * m + 1] +
                          ori[3 * n + 2] * ori[3 * m + 2])
                       : -1e30f;
    }
    __syncthreads();

    // ---- phase B: per-head online softmax, single pass ----
    const float* q     = g_qkv + ((size_t)h * N_TOK + n) * HIDD;
    const float* kbase = g_qkv + ((size_t)(NH + h)) * (size_t)N_TOK * HIDD;
    const float* vbase = g_qkv + ((size_t)(2 * NH + h)) * (size_t)N_TOK * HIDD;

    const float4 q4 = *(const float4*)(q + lane * 4);

    float  mx  = -1e30f;
    float  sum = 0.f;
    float4 acc = make_float4(0.f, 0.f, 0.f, 0.f);

    for (int j = 0; j < cnt; j++) {
        const float b = base[j];
        if (b < -1e29f) continue;          // warp-uniform skip
        const int m = m0 + j;

        float4 k4 = *(const float4*)(kbase + (size_t)m * HIDD + lane * 4);
        float d = q4.x * k4.x + q4.y * k4.y + q4.z * k4.z + q4.w * k4.w;
#pragma unroll
        for (int o2 = 16; o2; o2 >>= 1) d += __shfl_xor_sync(0xffffffffu, d, o2);
        const float s = d * 0.08838834764831843f + b;

        float4 v4 = *(const float4*)(vbase + (size_t)m * HIDD + lane * 4);
        if (s > mx) {                      // warp-uniform (s identical on all lanes)
            const float corr = expf(mx - s);   // 0 on first valid neighbor
            sum = sum * corr + 1.f;
            acc.x = acc.x * corr + v4.x;
            acc.y = acc.y * corr + v4.y;
            acc.z = acc.z * corr + v4.z;
            acc.w = acc.w * corr + v4.w;
            mx = s;
        } else {
            const float p = expf(s - mx);
            sum += p;
            acc.x = fmaf(p, v4.x, acc.x);
            acc.y = fmaf(p, v4.y, acc.y);
            acc.z = fmaf(p, v4.z, acc.z);
            acc.w = fmaf(p, v4.w, acc.w);
        }
    }

    const float inv = 1.f / sum;
    __half* op = g_oh + ((size_t)h * N_TOK + n) * HIDD;
    *(__half2*)(op + lane * 4)     = __float22half2_rn(make_float2(acc.x * inv, acc.y * inv));
    *(__half2*)(op + lane * 4 + 2) = __float22half2_rn(make_float2(acc.z * inv, acc.w * inv));
}

// ---------------- launch ----------------
extern "C" void kernel_launch(void* const* d_in, const int* in_sizes, int n_in,
                              void* d_out, int out_size)
{
    const float* x     = (const float*)d_in[0];
    const float* pos   = (const float*)d_in[1];
    const float* ori   = (const float*)d_in[2];
    // d_in[3] = seq == arange(N): the |ds|<=48 term is handled by the index band.
    const int*   batch = (const int*)d_in[4];
    const float* ln1_g = (const float*)d_in[5];
    const float* ln1_b = (const float*)d_in[6];
    const float* ln2_g = (const float*)d_in[7];
    const float* ln2_b = (const float*)d_in[8];
    const float* Wq    = (const float*)d_in[9];
    const float* Wk    = (const float*)d_in[10];
    const float* Wv    = (const float*)d_in[11];
    const float* Wo    = (const float*)d_in[12];
    const float* lnm_g = (const float*)d_in[13];
    const float* lnm_b = (const float*)d_in[14];
    const float* W1    = (const float*)d_in[15];
    const float* W2    = (const float*)d_in[16];
    float* out = (float*)d_out;

    __half *p_xnh, *p_h1h, *p_midnh, *p_wh;
    float  *p_x1, *p_mid;
    cudaGetSymbolAddress((void**)&p_xnh,   g_xnh);
    cudaGetSymbolAddress((void**)&p_x1,    g_x1);
    cudaGetSymbolAddress((void**)&p_h1h,   g_h1h);
    cudaGetSymbolAddress((void**)&p_mid,   g_mid);
    cudaGetSymbolAddress((void**)&p_midnh, g_midnh);
    cudaGetSymbolAddress((void**)&p_wh,    g_wh);

    // allow 80KB dynamic smem on the GEMM kernels (idempotent, capture-safe)
    static bool attr_done = false;
    if (!attr_done) {
        cudaFuncSetAttribute(sgemm_f16_kernel,
                             cudaFuncAttributeMaxDynamicSharedMemorySize, GEMM_SMEM);
        cudaFuncSetAttribute(qkv_kernel,
                             cudaFuncAttributeMaxDynamicSharedMemorySize, GEMM_SMEM);
        cudaFuncSetAttribute(wo_kernel,
                             cudaFuncAttributeMaxDynamicSharedMemorySize, GEMM_SMEM);
        attr_done = true;
    }

    // 0. transpose+convert all weights to fp16 [N][K]
    {
        dim3 tb(32, 8);
        transpose_h_kernel<<<dim3(16,  4, 4), tb>>>(Wq, p_wh + OWQ, CIN,  HIDD);
        transpose_h_kernel<<<dim3(16,  4, 4), tb>>>(Wk, p_wh + OWK, CIN,  HIDD);
        transpose_h_kernel<<<dim3(16,  4, 4), tb>>>(Wv, p_wh + OWV, CIN,  HIDD);
        transpose_h_kernel<<<dim3( 4,  4, 4), tb>>>(Wo, p_wh + OWO, HIDD, HIDD);
        transpose_h_kernel<<<dim3(16, 64, 1), tb>>>(W1, p_wh + OW1, CIN,  MIDC);
        transpose_h_kernel<<<dim3(64, 16, 1), tb>>>(W2, p_wh + OW2, MIDC, COUT);
    }

    // 1. xn = LN1(x), fp16
    ln_kernel<512, false><<<N_TOK, 128>>>(x, ln1_g, ln1_b, p_xnh);

    // 2. Q/K/V projections (batched, 384 CTAs, fp16 m16n8k16 + 4-stage cp.async)
    qkv_kernel<<<dim3(1, N_TOK / 128, 12), 256, GEMM_SMEM>>>();

    // 3. banded attention (single pass, shared mask/bias; fp32 math, fp16 output)
    attn_kernel<<<N_TOK, 128>>>(pos, ori, batch);

    // 4. x1 = concat_h(o_h @ Wo_h) + x
    wo_kernel<<<dim3(1, N_TOK / 128, 4), 256, GEMM_SMEM>>>(x);

    // 5. h1 = LN2(x1), fp16
    ln_kernel<512, false><<<N_TOK, 128>>>(p_x1, ln2_g, ln2_b, p_h1h);

    // 6. mid = h1 @ W1
    sgemm_f16_kernel<<<dim3(MIDC / 128, N_TOK / 128), 256, GEMM_SMEM>>>(
        p_h1h, CIN, p_wh + OW1, CIN, p_mid, MIDC, nullptr, CIN);

    // 7. midn = relu(LN_mid(mid)), fp16
    ln_kernel<2048, true><<<N_TOK, 128>>>(p_mid, lnm_g, lnm_b, p_midnh);

    // 8. out = midn @ W2 + x1
    sgemm_f16_kernel<<<dim3(COUT / 128, N_TOK / 128), 256, GEMM_SMEM>>>(
        p_midnh, MIDC, p_wh + OW2, MIDC, out, COUT, p_x1, MIDC);
}

// round 11
// speedup vs baseline: 4.9793x; 1.1060x over previous
#include <cuda_runtime.h>
#include <cuda_fp16.h>
#include <math.h>

#define N_TOK 4096
#define CIN   512
#define COUT  512
#define HIDD  128
#define NH    4
#define MIDC  2048
#define LWIN  48

// ---------------- scratch (device globals; no allocation allowed) ----------------
__device__ __half g_xnh [N_TOK * CIN];           // LN1(x), fp16
__device__ float  g_qkv [3 * NH * N_TOK * HIDD]; // q,k,v  [which][h][n][d] fp32
__device__ __half g_oh  [NH * N_TOK * HIDD];     // attention output, fp16
__device__ float  g_x1  [N_TOK * COUT];          // o@Wo + x (exact fp32)
__device__ __half g_h1h [N_TOK * COUT];          // LN2(x1), fp16
__device__ float  g_mid [N_TOK * MIDC];          // h1 @ W1 (fp32)
__device__ __half g_midnh[N_TOK * MIDC];         // relu(LN(mid)), fp16

// pre-transposed fp16 weights: each matrix stored [N][K] row-major
#define OWQ 0
#define OWK (OWQ + NH * CIN * HIDD)     // 262144
#define OWV (OWK + NH * CIN * HIDD)     // 524288
#define OWO (OWV + NH * CIN * HIDD)     // 786432
#define OW1 (OWO + NH * HIDD * HIDD)    // 851968
#define OW2 (OW1 + COUT * MIDC)         // 1900544
#define WTOT (OW2 + MIDC * COUT)        // 2949120
__device__ __half g_wh[WTOT];

// ---------------- fused weight transpose+convert: dst[n][k] = (half)src[k][n] ----
// One launch for all 6 weight tensors; flat 32x32-tile decode.
// tiles: Wq/Wk/Wv 3*4*64=768 | Wo 4*16=64 | W1 1024 | W2 1024  -> 2880 blocks
__global__ __launch_bounds__(256) void transpose_all_kernel(
    const float* __restrict__ Wq, const float* __restrict__ Wk,
    const float* __restrict__ Wv, const float* __restrict__ Wo,
    const float* __restrict__ W1, const float* __restrict__ W2)
{
    __shared__ float t[32][33];
    int bid = blockIdx.x;
    const float* src;
    __half* dst;
    int K, N, kt, nt;

    if (bid < 768) {                         // Wq/Wk/Wv: [512][128] x 4 heads each
        const int which = bid >> 8;          // 0..2
        const int rem   = bid & 255;
        const int mat   = rem >> 6;          // head 0..3
        const int tt    = rem & 63;
        K = CIN; N = HIDD; kt = tt & 15; nt = tt >> 4;
        src = (which == 0 ? Wq : which == 1 ? Wk : Wv) + (size_t)mat * CIN * HIDD;
        dst = g_wh + (size_t)which * (NH * CIN * HIDD) + (size_t)mat * CIN * HIDD;
    } else if (bid < 832) {                  // Wo: [128][128] x 4 heads
        const int rem = bid - 768;
        const int mat = rem >> 4;
        const int tt  = rem & 15;
        K = HIDD; N = HIDD; kt = tt & 3; nt = tt >> 2;
        src = Wo + (size_t)mat * HIDD * HIDD;
        dst = g_wh + OWO + (size_t)mat * HIDD * HIDD;
    } else if (bid < 1856) {                 // W1: [512][2048]
        const int tt = bid - 832;
        K = CIN; N = MIDC; kt = tt & 15; nt = tt >> 4;
        src = W1; dst = g_wh + OW1;
    } else {                                 // W2: [2048][512]
        const int tt = bid - 1856;
        K = MIDC; N = COUT; kt = tt & 63; nt = tt >> 6;
        src = W2; dst = g_wh + OW2;
    }

    const int k0 = kt * 32, n0 = nt * 32;
    const int tx = threadIdx.x & 31, ty = threadIdx.x >> 5;   // (32, 8)
#pragma unroll
    for (int i = 0; i < 32; i += 8)
        t[ty + i][tx] = src[(size_t)(k0 + ty + i) * N + n0 + tx];
    __syncthreads();
#pragma unroll
    for (int i = 0; i < 32; i += 8)
        dst[(size_t)(n0 + ty + i) * K + k0 + tx] = __float2half_rn(t[tx][ty + i]);
}

// ---------------- cp.async helpers ----------------
__device__ __forceinline__ unsigned s2u(const void* p) {
    return (unsigned)__cvta_generic_to_shared(p);
}
__device__ __forceinline__ void cpa16(unsigned dst, const void* src) {
    asm volatile("cp.async.cg.shared.global [%0], [%1], 16;\n" :: "r"(dst), "l"(src));
}
__device__ __forceinline__ void ldsm_x4(unsigned& r0, unsigned& r1,
                                        unsigned& r2, unsigned& r3, unsigned addr) {
    asm volatile("ldmatrix.sync.aligned.m8n8.x4.shared.b16 {%0,%1,%2,%3}, [%4];"
                 : "=r"(r0), "=r"(r1), "=r"(r2), "=r"(r3) : "r"(addr));
}

// ---------------- FP16 tensor-core GEMM: 128x128 tile, BK=32, 4-stage cp.async ---
// A: [M,K] row-major fp16; Bt: [N,K] row-major fp16 (pre-transposed weight);
// C = A@B (+ optional fp32 residual). blockDim=256 (8 warps 2x4), warp tile 64x32,
// mma.m16n8k16; fragments via ldmatrix.x4 (6 LDSM per 16 HMMA).
#define BKH  32
#define RS   40                          // smem row stride in halves (80B): LDSM phases conflict-free
#define NST  4
#define A_ST (128 * RS)                  // halves per stage (A and B identical)
#define GEMM_SMEM (NST * 2 * A_ST * 2)   // 81920 bytes

__device__ __forceinline__ void gemm_f16_body(
    const __half* __restrict__ A, int lda,
    const __half* __restrict__ Bt, int ldbt,
    float* __restrict__ C, int ldc,
    const float* __restrict__ Rsd,
    int K, int bm, int bn)
{
    extern __shared__ __half smh[];
    __half* As = smh;                    // [NST][128][RS]
    __half* Bs = smh + NST * A_ST;       // [NST][128][RS]

    const int tid   = threadIdx.x;
    const int wid   = tid >> 5;
    const int lane  = tid & 31;
    const int g     = lane >> 2;     // 0..7
    const int tg    = lane & 3;      // 0..3
    const int warpM = wid >> 2;      // 0..1  (64 rows)
    const int warpN = wid & 3;       // 0..3  (32 cols)

    const int lrow = tid >> 1;               // 0..127 (load row, A and B)
    const int lseg = (tid & 1) * 8;          // halves: 0 or 8

    const __half* Agp = A  + (size_t)(bm + lrow) * lda  + lseg;
    const __half* Bgp = Bt + (size_t)(bn + lrow) * ldbt + lseg;
    const unsigned saw = s2u(As + lrow * RS + lseg);
    const unsigned sbw = s2u(Bs + lrow * RS + lseg);

    // ldmatrix lane->address offsets (in halves)
    // A x4 tiles: (m0..7,kk),(m8..15,kk),(m0..7,kk+8),(m8..15,kk+8)
    const int a_lane = ((lane & 7) + ((lane & 8) ? 8 : 0)) * RS + ((lane & 16) ? 8 : 0);
    // B x4 tiles: (n0..7,kk),(n0..7,kk+8),(n8..15,kk),(n8..15,kk+8)
    const int b_lane = ((lane & 7) + ((lane & 16) ? 8 : 0)) * RS + ((lane & 8) ? 8 : 0);

    const unsigned abase0 = s2u(As) + (unsigned)(warpM * 64 * RS + a_lane) * 2;
    const unsigned bbase0 = s2u(Bs) + (unsigned)(warpN * 32 * RS + b_lane) * 2;

    const int nchunks = K / BKH;

#define ISSUE(c)                                                            \
    do {                                                                    \
        const unsigned _off = ((c) & (NST - 1)) * (A_ST * 2);               \
        const int _kn = (c) * BKH;                                          \
        cpa16(saw + _off,      Agp + _kn);                                  \
        cpa16(saw + _off + 32, Agp + _kn + 16);                             \
        cpa16(sbw + _off,      Bgp + _kn);                                  \
        cpa16(sbw + _off + 32, Bgp + _kn + 16);                             \
        asm volatile("cp.async.commit_group;\n" ::: "memory");              \
    } while (0)

    float acc[4][4][4];
#pragma unroll
    for (int mi = 0; mi < 4; mi++)
#pragma unroll
        for (int ni = 0; ni < 4; ni++)
#pragma unroll
            for (int r = 0; r < 4; r++) acc[mi][ni][r] = 0.f;

    // prologue: 3 chunks in flight (nchunks >= 4 for all shapes here)
    ISSUE(0);
    ISSUE(1);
    ISSUE(2);

    for (int c = 0; c < nchunks; c++) {
        asm volatile("cp.async.wait_group 2;\n" ::: "memory");
        __syncthreads();

        const unsigned aslot = abase0 + ((c & (NST - 1)) * (A_ST * 2));
        const unsigned bslot = bbase0 + ((c & (NST - 1)) * (A_ST * 2));

#pragma unroll
        for (int ks = 0; ks < 2; ks++) {
            const int kk = ks * 16;
            unsigned af[4][4], bf[4][2];
#pragma unroll
            for (int mi = 0; mi < 4; mi++)
                ldsm_x4(af[mi][0], af[mi][1], af[mi][2], af[mi][3],
                        aslot + (unsigned)(mi * 16 * RS + kk) * 2);
#pragma unroll
            for (int nip = 0; nip < 2; nip++)
                ldsm_x4(bf[2 * nip][0], bf[2 * nip][1],
                        bf[2 * nip + 1][0], bf[2 * nip + 1][1],
                        bslot + (unsigned)(nip * 16 * RS + kk) * 2);
#pragma unroll
            for (int mi = 0; mi < 4; mi++)
#pragma unroll
                for (int ni = 0; ni < 4; ni++)
                    asm volatile(
                        "mma.sync.aligned.m16n8k16.row.col.f32.f16.f16.f32 "
                        "{%0,%1,%2,%3}, {%4,%5,%6,%7}, {%8,%9}, {%0,%1,%2,%3};"
                        : "+f"(acc[mi][ni][0]), "+f"(acc[mi][ni][1]),
                          "+f"(acc[mi][ni][2]), "+f"(acc[mi][ni][3])
                        : "r"(af[mi][0]), "r"(af[mi][1]), "r"(af[mi][2]), "r"(af[mi][3]),
                          "r"(bf[ni][0]), "r"(bf[ni][1]));
        }

        // keep commit-group count in lockstep (empty group at the tail)
        if (c + 3 < nchunks) {
            ISSUE(c + 3);
        } else {
            asm volatile("cp.async.commit_group;\n" ::: "memory");
        }
    }
#undef ISSUE

    // ---- epilogue: C = acc (+ Rsd) ----
#pragma unroll
    for (int mi = 0; mi < 4; mi++) {
        const int r0 = bm + warpM * 64 + mi * 16 + g;
#pragma unroll
        for (int ni = 0; ni < 4; ni++) {
            const int c0 = bn + warpN * 32 + ni * 8 + tg * 2;
            float2 lo = make_float2(acc[mi][ni][0], acc[mi][ni][1]);
            float2 hi = make_float2(acc[mi][ni][2], acc[mi][ni][3]);
            if (Rsd) {
                float2 rl = *(const float2*)(Rsd + (size_t)r0 * ldc + c0);
                float2 rh = *(const float2*)(Rsd + (size_t)(r0 + 8) * ldc + c0);
                lo.x += rl.x; lo.y += rl.y;
                hi.x += rh.x; hi.y += rh.y;
            }
            *(float2*)(C + (size_t)r0 * ldc + c0)       = lo;
            *(float2*)(C + (size_t)(r0 + 8) * ldc + c0) = hi;
        }
    }
}

__global__ __launch_bounds__(256, 2) void sgemm_f16_kernel(
    const __half* __restrict__ A, int lda, const __half* __restrict__ Bt, int ldbt,
    float* __restrict__ C, int ldc, const float* __restrict__ Rsd, int K)
{
    gemm_f16_body(A, lda, Bt, ldbt, C, ldc, Rsd, K, blockIdx.y * 128, blockIdx.x * 128);
}

// QKV: z = which*4 + h ; C[h,n,d] = xn @ W_which[h]   (batched: grid.z = 12)
__global__ __launch_bounds__(256, 2) void qkv_kernel()
{
    const int z = blockIdx.z;
    const int which = z >> 2, h = z & 3;
    const __half* Bt = g_wh + (size_t)which * (NH * CIN * HIDD) + (size_t)h * CIN * HIDD;
    float* C = g_qkv + ((size_t)which * NH + h) * (size_t)N_TOK * HIDD;
    gemm_f16_body(g_xnh, CIN, Bt, CIN, C, HIDD, nullptr, CIN, blockIdx.y * 128, 0);
}

// Wo + residual x: x1[n, h*128+e] = o_h @ Wo_h + x[n, h*128+e]   (grid.z = 4)
__global__ __launch_bounds__(256, 2) void wo_kernel(const float* __restrict__ xres)
{
    const int h = blockIdx.z;
    gemm_f16_body(g_oh + (size_t)h * N_TOK * HIDD, HIDD,
                  g_wh + OWO + (size_t)h * HIDD * HIDD, HIDD,
                  g_x1 + h * HIDD, COUT,
                  xres + h * HIDD, HIDD, blockIdx.y * 128, 0);
}

// ---------------- LayerNorm (block per row; row in registers; fp16 output) -------
template <int C, bool RELU>
__global__ __launch_bounds__(128) void ln_kernel(
    const float* __restrict__ x, const float* __restrict__ g,
    const float* __restrict__ b, __half* __restrict__ out)
{
    __shared__ float sbuf[4];
    const int tid = threadIdx.x;
    const float* xr = x + (size_t)blockIdx.x * C;
    constexpr int NV = C / 512;   // float4 chunks per thread

    float4 v[NV];
    float s = 0.f;
#pragma unroll
    for (int i = 0; i < NV; i++) {
        v[i] = *(const float4*)(xr + (i * 128 + tid) * 4);
        s += v[i].x + v[i].y + v[i].z + v[i].w;
    }
#pragma unroll
    for (int o2 = 16; o2; o2 >>= 1) s += __shfl_xor_sync(0xffffffffu, s, o2);
    if ((tid & 31) == 0) sbuf[tid >> 5] = s;
    __syncthreads();
    const float mean = (sbuf[0] + sbuf[1] + sbuf[2] + sbuf[3]) * (1.f / C);
    __syncthreads();

    float vs = 0.f;
#pragma unroll
    for (int i = 0; i < NV; i++) {
        float dx;
        dx = v[i].x - mean; vs += dx * dx;
        dx = v[i].y - mean; vs += dx * dx;
        dx = v[i].z - mean; vs += dx * dx;
        dx = v[i].w - mean; vs += dx * dx;
    }
#pragma unroll
    for (int o2 = 16; o2; o2 >>= 1) vs += __shfl_xor_sync(0xffffffffu, vs, o2);
    if ((tid & 31) == 0) sbuf[tid >> 5] = vs;
    __syncthreads();
    const float var  = (sbuf[0] + sbuf[1] + sbuf[2] + sbuf[3]) * (1.f / C);
    const float rstd = 1.f / sqrtf(var + 1e-5f);

    __half* orow = out + (size_t)blockIdx.x * C;
#pragma unroll
    for (int i = 0; i < NV; i++) {
        const int idx = (i * 128 + tid) * 4;
        float4 gg = *(const float4*)(g + idx);
        float4 bb = *(const float4*)(b + idx);
        float4 r;
        r.x = (v[i].x - mean) * rstd * gg.x + bb.x;
        r.y = (v[i].y - mean) * rstd * gg.y + bb.y;
        r.z = (v[i].z - mean) * rstd * gg.z + bb.z;
        r.w = (v[i].w - mean) * rstd * gg.w + bb.w;
        if (RELU) {
            r.x = fmaxf(r.x, 0.f); r.y = fmaxf(r.y, 0.f);
            r.z = fmaxf(r.z, 0.f); r.w = fmaxf(r.w, 0.f);
        }
        __half2 h0 = __float22half2_rn(make_float2(r.x, r.y));
        __half2 h1 = __float22half2_rn(make_float2(r.z, r.w));
        *(__half2*)(orow + idx)     = h0;
        *(__half2*)(orow + idx + 2) = h1;
    }
}

// ---------------- banded attention: 1 block / query, 1 warp / head ----------------
// Phase A: mask+gbias computed ONCE per (n,m) pair (head-independent), in smem.
// Phase B: per-head single pass with online softmax (rescale on new max).
// Skipping masked entries is exact: expf(-1e9 - max) == 0 in fp32.
__global__ __launch_bounds__(128) void attn_kernel(
    const float* __restrict__ pos, const float* __restrict__ ori,
    const int* __restrict__ batch)
{
    const int n    = blockIdx.x;
    const int tid  = threadIdx.x;
    const int h    = tid >> 5;
    const int lane = tid & 31;
    __shared__ float base[2 * LWIN + 1];

    const int m0  = (n - LWIN < 0) ? 0 : n - LWIN;
    const int m1  = (n + LWIN > N_TOK - 1) ? N_TOK - 1 : n + LWIN;
    const int cnt = m1 - m0 + 1;

    // ---- phase A: head-independent mask + orientation bias ----
    if (tid < cnt) {
        const int m = m0 + tid;
        const float dx = pos[3 * m]     - pos[3 * n];
        const float dy = pos[3 * m + 1] - pos[3 * n + 1];
        const float dz = pos[3 * m + 2] - pos[3 * n + 2];
        const bool ok = (batch[m] == batch[n]) && (dx * dx + dy * dy + dz * dz <= 1.0f);
        base[tid] = ok ? (ori[3 * n]     * ori[3 * m] +
                          ori[3 * n + 1] * ori[3 * m + 1] +
                          ori[3 * n + 2] * ori[3 * m + 2])
                       : -1e30f;
    }
    __syncthreads();

    // ---- phase B: per-head online softmax, single pass ----
    const float* q     = g_qkv + ((size_t)h * N_TOK + n) * HIDD;
    const float* kbase = g_qkv + ((size_t)(NH + h)) * (size_t)N_TOK * HIDD;
    const float* vbase = g_qkv + ((size_t)(2 * NH + h)) * (size_t)N_TOK * HIDD;

    const float4 q4 = *(const float4*)(q + lane * 4);

    float  mx  = -1e30f;
    float  sum = 0.f;
    float4 acc = make_float4(0.f, 0.f, 0.f, 0.f);

    for (int j = 0; j < cnt; j++) {
        const float b = base[j];
        if (b < -1e29f) continue;          // warp-uniform skip
        const int m = m0 + j;

        float4 k4 = *(const float4*)(kbase + (size_t)m * HIDD + lane * 4);
        float d = q4.x * k4.x + q4.y * k4.y + q4.z * k4.z + q4.w * k4.w;
#pragma unroll
        for (int o2 = 16; o2; o2 >>= 1) d += __shfl_xor_sync(0xffffffffu, d, o2);
        const float s = d * 0.08838834764831843f + b;

        float4 v4 = *(const float4*)(vbase + (size_t)m * HIDD + lane * 4);
        if (s > mx) {                      // warp-uniform (s identical on all lanes)
            const float corr = expf(mx - s);   // 0 on first valid neighbor
            sum = sum * corr + 1.f;
            acc.x = acc.x * corr + v4.x;
            acc.y = acc.y * corr + v4.y;
            acc.z = acc.z * corr + v4.z;
            acc.w = acc.w * corr + v4.w;
            mx = s;
        } else {
            const float p = expf(s - mx);
            sum += p;
            acc.x = fmaf(p, v4.x, acc.x);
            acc.y = fmaf(p, v4.y, acc.y);
            acc.z = fmaf(p, v4.z, acc.z);
            acc.w = fmaf(p, v4.w, acc.w);
        }
    }

    const float inv = 1.f / sum;
    __half* op = g_oh + ((size_t)h * N_TOK + n) * HIDD;
    *(__half2*)(op + lane * 4)     = __float22half2_rn(make_float2(acc.x * inv, acc.y * inv));
    *(__half2*)(op + lane * 4 + 2) = __float22half2_rn(make_float2(acc.z * inv, acc.w * inv));
}

// ---------------- launch ----------------
extern "C" void kernel_launch(void* const* d_in, const int* in_sizes, int n_in,
                              void* d_out, int out_size)
{
    const float* x     = (const float*)d_in[0];
    const float* pos   = (const float*)d_in[1];
    const float* ori   = (const float*)d_in[2];
    // d_in[3] = seq == arange(N): the |ds|<=48 term is handled by the index band.
    const int*   batch = (const int*)d_in[4];
    const float* ln1_g = (const float*)d_in[5];
    const float* ln1_b = (const float*)d_in[6];
    const float* ln2_g = (const float*)d_in[7];
    const float* ln2_b = (const float*)d_in[8];
    const float* Wq    = (const float*)d_in[9];
    const float* Wk    = (const float*)d_in[10];
    const float* Wv    = (const float*)d_in[11];
    const float* Wo    = (const float*)d_in[12];
    const float* lnm_g = (const float*)d_in[13];
    const float* lnm_b = (const float*)d_in[14];
    const float* W1    = (const float*)d_in[15];
    const float* W2    = (const float*)d_in[16];
    float* out = (float*)d_out;

    __half *p_xnh, *p_h1h, *p_midnh, *p_wh;
    float  *p_x1, *p_mid;
    cudaGetSymbolAddress((void**)&p_xnh,   g_xnh);
    cudaGetSymbolAddress((void**)&p_x1,    g_x1);
    cudaGetSymbolAddress((void**)&p_h1h,   g_h1h);
    cudaGetSymbolAddress((void**)&p_mid,   g_mid);
    cudaGetSymbolAddress((void**)&p_midnh, g_midnh);
    cudaGetSymbolAddress((void**)&p_wh,    g_wh);

    // allow 80KB dynamic smem on the GEMM kernels (idempotent, capture-safe)
    static bool attr_done = false;
    if (!attr_done) {
        cudaFuncSetAttribute(sgemm_f16_kernel,
                             cudaFuncAttributeMaxDynamicSharedMemorySize, GEMM_SMEM);
        cudaFuncSetAttribute(qkv_kernel,
                             cudaFuncAttributeMaxDynamicSharedMemorySize, GEMM_SMEM);
        cudaFuncSetAttribute(wo_kernel,
                             cudaFuncAttributeMaxDynamicSharedMemorySize, GEMM_SMEM);
        attr_done = true;
    }

    // 0. transpose+convert all weights to fp16 [N][K] (single launch, 2880 tiles)
    transpose_all_kernel<<<2880, 256>>>(Wq, Wk, Wv, Wo, W1, W2);

    // 1. xn = LN1(x), fp16
    ln_kernel<512, false><<<N_TOK, 128>>>(x, ln1_g, ln1_b, p_xnh);

    // 2. Q/K/V projections (batched, 384 CTAs, fp16 m16n8k16 + ldmatrix)
    qkv_kernel<<<dim3(1, N_TOK / 128, 12), 256, GEMM_SMEM>>>();

    // 3. banded attention (single pass, shared mask/bias; fp32 math, fp16 output)
    attn_kernel<<<N_TOK, 128>>>(pos, ori, batch);

    // 4. x1 = concat_h(o_h @ Wo_h) + x
    wo_kernel<<<dim3(1, N_TOK / 128, 4), 256, GEMM_SMEM>>>(x);

    // 5. h1 = LN2(x1), fp16
    ln_kernel<512, false><<<N_TOK, 128>>>(p_x1, ln2_g, ln2_b, p_h1h);

    // 6. mid = h1 @ W1
    sgemm_f16_kernel<<<dim3(MIDC / 128, N_TOK / 128), 256, GEMM_SMEM>>>(
        p_h1h, CIN, p_wh + OW1, CIN, p_mid, MIDC, nullptr, CIN);

    // 7. midn = relu(LN_mid(mid)), fp16
    ln_kernel<2048, true><<<N_TOK, 128>>>(p_mid, lnm_g, lnm_b, p_midnh);

    // 8. out = midn @ W2 + x1
    sgemm_f16_kernel<<<dim3(COUT / 128, N_TOK / 128), 256, GEMM_SMEM>>>(
        p_midnh, MIDC, p_wh + OW2, MIDC, out, COUT, p_x1, MIDC);
}